// round 10
// baseline (speedup 1.0000x reference)
#include <cuda_runtime.h>
#include <cstdint>

// Problem constants
constexpr int kB = 4;
constexpr int kN = 1024;
constexpr int kD = 256;
constexpr int kH = 8;
constexpr int kDH  = kD * kH;          // 2048
constexpr int kNDH = kN * kDH;         // 2097152
constexpr int kSeg = kB * kNDH;        // 8388608  (q/k/v segment, floats)
constexpr int kC3  = 3 * kDH;          // 6144
constexpr int kRows = kB * kN;         // 4096

// Scratch (device globals; no dynamic allocation allowed)
__device__ float g_qkv[3ull * kSeg];   // ~100.7 MB : QKV in reference flat layout
__device__ float g_qkT[2ull * kSeg];   // seg0: Q n-major scaled [bh][n][d]
                                       // seg1: K d-major       [bh][d][n]
__device__ float g_diag[kRows * kH];
__device__ float g_part4[4][kRows * kD];  // k3 K-split partials

// ---------------- cp.async helpers ----------------
__device__ __forceinline__ void cp16(void* smem_dst, const void* gmem_src) {
    unsigned s = (unsigned)__cvta_generic_to_shared(smem_dst);
    asm volatile("cp.async.cg.shared.global [%0], [%1], 16;\n" :: "r"(s), "l"(gmem_src));
}
__device__ __forceinline__ void cp_commit() {
    asm volatile("cp.async.commit_group;\n");
}
template <int N>
__device__ __forceinline__ void cp_wait() {
    asm volatile("cp.async.wait_group %0;\n" :: "n"(N));
}

// ---------------- packed f32x2 helpers (Blackwell FFMA2) ----------------
__device__ __forceinline__ void ffma2(uint64_t& d, uint64_t a, uint64_t b) {
    asm("fma.rn.f32x2 %0, %1, %2, %0;" : "+l"(d) : "l"(a), "l"(b));
}
__device__ __forceinline__ uint64_t bcast2(float x) {
    uint64_t r;
    asm("mov.b64 %0, {%1, %1};" : "=l"(r) : "r"(__float_as_uint(x)));
    return r;
}
__device__ __forceinline__ float2 unpk2(uint64_t v) {
    uint32_t lo, hi;
    asm("mov.b64 {%0, %1}, %2;" : "=r"(lo), "=r"(hi) : "l"(v));
    return make_float2(__uint_as_float(lo), __uint_as_float(hi));
}
__device__ __forceinline__ float selc(float4 v, int kk) {
    return (kk == 0) ? v.x : (kk == 1) ? v.y : (kk == 2) ? v.z : v.w;
}

// ---------------------------------------------------------------------------
// Kernel 1: QKV = x @ Wqkv + bqkv     [4096,256] @ [256,6144]
// CTA 64m x 128n, microtile 4x8 packed, 3 CTAs/SM target. grid(48, 64).
// ---------------------------------------------------------------------------
__global__ __launch_bounds__(256, 3)
void qkv_gemm_kernel(const float* __restrict__ x,
                     const float* __restrict__ W,
                     const float* __restrict__ bias)
{
    extern __shared__ float sm[];
    float* As = sm;                 // [2][64*36]
    float* Bs = sm + 2 * 2304;      // [2][32*132]

    const int t  = threadIdx.x;
    const int tx = t & 15, ty = t >> 4;
    const int r0 = blockIdx.y * 64;
    const int c0 = blockIdx.x * 128;

    const int ar = t >> 3, ap = t & 7;    // A loader: rows ar+32j, f4 part ap
    const int bp = t & 31, br = t >> 5;   // B loader: f4 part bp, k rows br+8i

    uint64_t acc[4][4] = {};

#pragma unroll
    for (int j = 0; j < 2; j++) {
        int m = ar + 32 * j;
        cp16(&As[m * 36 + ap * 4], &x[(size_t)(r0 + m) * kD + ap * 4]);
    }
#pragma unroll
    for (int i = 0; i < 4; i++) {
        int k = br + 8 * i;
        cp16(&Bs[k * 132 + bp * 4], &W[(size_t)k * kC3 + c0 + bp * 4]);
    }
    cp_commit();

    for (int c = 0; c < 8; c++) {
        const int buf = c & 1;
        if (c < 7) {
            const int kc = (c + 1) * 32;
            const int nb = buf ^ 1;
#pragma unroll
            for (int j = 0; j < 2; j++) {
                int m = ar + 32 * j;
                cp16(&As[nb * 2304 + m * 36 + ap * 4],
                     &x[(size_t)(r0 + m) * kD + kc + ap * 4]);
            }
#pragma unroll
            for (int i = 0; i < 4; i++) {
                int k = br + 8 * i;
                cp16(&Bs[nb * 4224 + k * 132 + bp * 4],
                     &W[(size_t)(kc + k) * kC3 + c0 + bp * 4]);
            }
            cp_commit();
            cp_wait<1>();
        } else {
            cp_wait<0>();
        }
        __syncthreads();

        const float* A_ = &As[buf * 2304];
        const float* B_ = &Bs[buf * 4224];
#pragma unroll
        for (int kg = 0; kg < 32; kg += 4) {
            float4 av[4];
#pragma unroll
            for (int i = 0; i < 4; i++)
                av[i] = *(const float4*)&A_[(ty * 4 + i) * 36 + kg];
#pragma unroll
            for (int kk = 0; kk < 4; kk++) {
                ulonglong2 p0 = *(const ulonglong2*)&B_[(kg + kk) * 132 + tx * 4];
                ulonglong2 p1 = *(const ulonglong2*)&B_[(kg + kk) * 132 + tx * 4 + 64];
#pragma unroll
                for (int i = 0; i < 4; i++) {
                    uint64_t a2 = bcast2(selc(av[i], kk));
                    ffma2(acc[i][0], a2, p0.x);
                    ffma2(acc[i][1], a2, p0.y);
                    ffma2(acc[i][2], a2, p1.x);
                    ffma2(acc[i][3], a2, p1.y);
                }
            }
        }
        __syncthreads();
    }

#pragma unroll
    for (int i = 0; i < 4; i++) {
        int r = r0 + ty * 4 + i;
#pragma unroll
        for (int gj = 0; gj < 2; gj++) {
            int c = c0 + gj * 64 + tx * 4;
            float2 u0 = unpk2(acc[i][gj * 2 + 0]);
            float2 u1 = unpk2(acc[i][gj * 2 + 1]);
            float4 v;
            v.x = u0.x + bias[c + 0];
            v.y = u0.y + bias[c + 1];
            v.z = u1.x + bias[c + 2];
            v.w = u1.y + bias[c + 3];
            *(float4*)&g_qkv[(size_t)r * kC3 + c] = v;
        }
    }
}

// ---------------------------------------------------------------------------
// Transpose: q -> [bh][n][d] (scaled 1/16);  k -> [bh][d][n] (d-major).
// ---------------------------------------------------------------------------
__global__ __launch_bounds__(256)
void transpose_qk_kernel()
{
    __shared__ float smt[8][32][33];   // [h][qd][n]
    const int bid = blockIdx.x;
    const int qb  = bid & 7;
    const int nb  = (bid >> 3) & 31;
    const int b   = (bid >> 8) & 3;
    const int seg = bid >> 10;
    const int t   = threadIdx.x;

    const float* src = g_qkv + (size_t)seg * kSeg + (size_t)b * kNDH
                     + (size_t)(nb * 32) * kDH + qb * 32 * 8;
    {
        const int nl = t >> 3, f = t & 7;
        const int h0 = (f & 1) * 4, q0 = f >> 1;
#pragma unroll
        for (int i = 0; i < 8; i++) {
            float4 v = *(const float4*)&src[(size_t)nl * kDH + (f + i * 8) * 4];
            int ql = q0 + i * 4;
            smt[h0 + 0][ql][nl] = v.x;
            smt[h0 + 1][ql][nl] = v.y;
            smt[h0 + 2][ql][nl] = v.z;
            smt[h0 + 3][ql][nl] = v.w;
        }
    }
    __syncthreads();
    if (seg == 0) {
        // Q: n-major [bh][n][qd], scaled by 1/16
        const int q4 = (t & 7) * 4, hn = t >> 3;
#pragma unroll
        for (int i = 0; i < 8; i++) {
            int idx = hn + i * 32;
            int h = idx >> 5, n = idx & 31;
            float4 v;
            v.x = smt[h][q4 + 0][n] * 0.0625f;
            v.y = smt[h][q4 + 1][n] * 0.0625f;
            v.z = smt[h][q4 + 2][n] * 0.0625f;
            v.w = smt[h][q4 + 3][n] * 0.0625f;
            float* dst = g_qkT
                       + (((size_t)(b * 8 + h) * kN + nb * 32 + n) * kD)
                       + qb * 32 + q4;
            *(float4*)dst = v;
        }
    } else {
        // K: d-major [bh][qd][n]
#pragma unroll
        for (int i = 0; i < 8; i++) {
            int idx = t + i * 256;          // 0..2047
            int h = idx >> 8, rem = idx & 255;
            int q = rem >> 3, nf = rem & 7;
            float4 v;
            v.x = smt[h][q][nf * 4 + 0];
            v.y = smt[h][q][nf * 4 + 1];
            v.z = smt[h][q][nf * 4 + 2];
            v.w = smt[h][q][nf * 4 + 3];
            float* dst = g_qkT + (size_t)kSeg
                       + (((size_t)(b * 8 + h) * kD + qb * 32 + q) * kN)
                       + nb * 32 + nf * 4;
            *(float4*)dst = v;
        }
    }
}

// ---------------------------------------------------------------------------
// Kernel 2: per (b,h): S[m,n] = qs_m . k_n; column softmax over m (no max
// pass: |S| <~ 1); keep diagonal attn. CTA: 128 n-cols, m in 16 tiles of 64.
// Microtile 4x8 packed; both operands direct cp.async. grid(8, 32).
// ---------------------------------------------------------------------------
__global__ __launch_bounds__(256, 3)
void score_diag_kernel()
{
    extern __shared__ float sm[];
    float* As     = sm;                  // [2][64*36]
    float* Ks     = sm + 2 * 2304;       // [2][32*132]
    float* red    = sm + 2 * 2304 + 2 * 4224;  // [16*128]
    float* diagsm = red + 2048;          // [128]

    const int t  = threadIdx.x;
    const int tx = t & 15, ty = t >> 4;
    const int bh = blockIdx.y;
    const int b  = bh >> 3, h = bh & 7;
    const int n0 = blockIdx.x * 128;

    const float* Q  = g_qkT + (size_t)bh * (kN * kD);           // [n][d], scaled
    const float* Kd = g_qkT + (size_t)kSeg + (size_t)bh * (kD * kN);  // [d][n]

    const int ar = t >> 3, ap = t & 7;
    const int bp = t & 31, br = t >> 5;

    float colsum[8];
#pragma unroll
    for (int j = 0; j < 8; j++) colsum[j] = 0.f;

    for (int mt = 0; mt < 16; mt++) {
        const int m0 = mt * 64;
        uint64_t acc[4][4] = {};

#pragma unroll
        for (int j = 0; j < 2; j++) {
            int m = ar + 32 * j;
            cp16(&As[m * 36 + ap * 4], &Q[(size_t)(m0 + m) * kD + ap * 4]);
        }
#pragma unroll
        for (int i = 0; i < 4; i++) {
            int k = br + 8 * i;
            cp16(&Ks[k * 132 + bp * 4], &Kd[(size_t)k * kN + n0 + bp * 4]);
        }
        cp_commit();

        for (int c = 0; c < 8; c++) {
            const int buf = c & 1;
            if (c < 7) {
                const int kc = (c + 1) * 32;
                const int nb = buf ^ 1;
#pragma unroll
                for (int j = 0; j < 2; j++) {
                    int m = ar + 32 * j;
                    cp16(&As[nb * 2304 + m * 36 + ap * 4],
                         &Q[(size_t)(m0 + m) * kD + kc + ap * 4]);
                }
#pragma unroll
                for (int i = 0; i < 4; i++) {
                    int k = br + 8 * i;
                    cp16(&Ks[nb * 4224 + k * 132 + bp * 4],
                         &Kd[(size_t)(kc + k) * kN + n0 + bp * 4]);
                }
                cp_commit();
                cp_wait<1>();
            } else {
                cp_wait<0>();
            }
            __syncthreads();

            const float* A_ = &As[buf * 2304];
            const float* K_ = &Ks[buf * 4224];
#pragma unroll
            for (int kg = 0; kg < 32; kg += 4) {
                float4 av[4];
#pragma unroll
                for (int i = 0; i < 4; i++)
                    av[i] = *(const float4*)&A_[(ty * 4 + i) * 36 + kg];
#pragma unroll
                for (int kk = 0; kk < 4; kk++) {
                    ulonglong2 p0 = *(const ulonglong2*)&K_[(kg + kk) * 132 + tx * 4];
                    ulonglong2 p1 = *(const ulonglong2*)&K_[(kg + kk) * 132 + tx * 4 + 64];
#pragma unroll
                    for (int i = 0; i < 4; i++) {
                        uint64_t a2 = bcast2(selc(av[i], kk));
                        ffma2(acc[i][0], a2, p0.x);
                        ffma2(acc[i][1], a2, p0.y);
                        ffma2(acc[i][2], a2, p1.x);
                        ffma2(acc[i][3], a2, p1.y);
                    }
                }
            }
            __syncthreads();
        }

        // ---- epilogue: exp + colsum (registers); diagonal -> smem ----
        const bool diagtile = ((mt >> 1) == (int)blockIdx.x);
#pragma unroll
        for (int jp = 0; jp < 4; jp++) {
            int cl0 = (jp >> 1) * 64 + tx * 4 + (jp & 1) * 2;
            float s0 = 0.f, s1 = 0.f;
#pragma unroll
            for (int i = 0; i < 4; i++) {
                float2 u = unpk2(acc[i][jp]);
                float e0 = __expf(u.x), e1 = __expf(u.y);
                s0 += e0; s1 += e1;
                if (diagtile) {
                    int gm = m0 + ty * 4 + i;
                    if (gm == n0 + cl0)     diagsm[cl0]     = e0;
                    if (gm == n0 + cl0 + 1) diagsm[cl0 + 1] = e1;
                }
            }
            colsum[2 * jp]     += s0;
            colsum[2 * jp + 1] += s1;
        }
    }

    // ---- single final reduction across the 16 ty-groups ----
#pragma unroll
    for (int jp = 0; jp < 4; jp++) {
        int cl = (jp >> 1) * 64 + tx * 4 + (jp & 1) * 2;
        red[ty * 128 + cl]     = colsum[2 * jp];
        red[ty * 128 + cl + 1] = colsum[2 * jp + 1];
    }
    __syncthreads();
    if (t < 128) {
        float total = red[t];
#pragma unroll
        for (int r = 1; r < 16; r++) total += red[r * 128 + t];
        g_diag[((size_t)b * kN + (n0 + t)) * kH + h] = diagsm[t] / total;
    }
}

// ---------------------------------------------------------------------------
// Kernel 3: partial = (diag .* v) @ W0, K-split 4.  [4096,2048]@[2048,256]
// CTA 64m x 128n over a 512-wide K slice; A fused diag multiply via LDG+STS.
// grid(2 ctiles, 64 mtiles, 4 ksplit) = 512 CTAs.
// ---------------------------------------------------------------------------
__global__ __launch_bounds__(256, 3)
void out_gemm_kernel(const float* __restrict__ W0)
{
    extern __shared__ float sm[];
    float* As  = sm;                   // [2][64*36]
    float* Ws  = sm + 2 * 2304;        // [2][32*132]
    float* dsm = sm + 2 * 2304 + 2 * 4224;  // [64*8]

    const int t  = threadIdx.x;
    const int tx = t & 15, ty = t >> 4;
    const int c0 = blockIdx.x * 128;
    const int r0 = blockIdx.y * 64;
    const int kb = blockIdx.z * 512;
    const float* vseg = g_qkv + 2ull * kSeg;
    float* dst = g_part4[blockIdx.z];

    for (int idx = t; idx < 512; idx += 256)
        dsm[idx] = g_diag[(size_t)(r0 + (idx >> 3)) * kH + (idx & 7)];

    const int ar = t >> 3, ap = t & 7;
    const int bp = t & 31, br = t >> 5;

    uint64_t acc[4][4] = {};

    // preload chunk 0
    float4 areg[2];
#pragma unroll
    for (int i = 0; i < 4; i++) {
        int k = br + 8 * i;
        cp16(&Ws[k * 132 + bp * 4], &W0[(size_t)(kb + k) * kD + c0 + bp * 4]);
    }
    cp_commit();
#pragma unroll
    for (int j = 0; j < 2; j++) {
        int m = ar + 32 * j;
        areg[j] = *(const float4*)&vseg[(size_t)(r0 + m) * kDH + kb + ap * 4];
    }
    __syncthreads();   // dsm ready

    for (int c = 0; c < 16; c++) {
        const int buf = c & 1;
        {
            const int hoff = (ap & 1) * 4;
#pragma unroll
            for (int j = 0; j < 2; j++) {
                int m = ar + 32 * j;
                float4 dv = *(const float4*)&dsm[m * 8 + hoff];
                float4 v = areg[j];
                v.x *= dv.x; v.y *= dv.y; v.z *= dv.z; v.w *= dv.w;
                *(float4*)&As[buf * 2304 + m * 36 + ap * 4] = v;
            }
        }
        if (c < 15) {
            const int kc = (c + 1) * 32;
#pragma unroll
            for (int i = 0; i < 4; i++) {
                int k = br + 8 * i;
                cp16(&Ws[(buf ^ 1) * 4224 + k * 132 + bp * 4],
                     &W0[(size_t)(kb + kc + k) * kD + c0 + bp * 4]);
            }
            cp_commit();
#pragma unroll
            for (int j = 0; j < 2; j++) {
                int m = ar + 32 * j;
                areg[j] = *(const float4*)
                    &vseg[(size_t)(r0 + m) * kDH + kb + kc + ap * 4];
            }
            cp_wait<1>();
        } else {
            cp_wait<0>();
        }
        __syncthreads();

        const float* A_ = &As[buf * 2304];
        const float* W_ = &Ws[buf * 4224];
#pragma unroll
        for (int kg = 0; kg < 32; kg += 4) {
            float4 av[4];
#pragma unroll
            for (int i = 0; i < 4; i++)
                av[i] = *(const float4*)&A_[(ty * 4 + i) * 36 + kg];
#pragma unroll
            for (int kk = 0; kk < 4; kk++) {
                ulonglong2 p0 = *(const ulonglong2*)&W_[(kg + kk) * 132 + tx * 4];
                ulonglong2 p1 = *(const ulonglong2*)&W_[(kg + kk) * 132 + tx * 4 + 64];
#pragma unroll
                for (int i = 0; i < 4; i++) {
                    uint64_t a2 = bcast2(selc(av[i], kk));
                    ffma2(acc[i][0], a2, p0.x);
                    ffma2(acc[i][1], a2, p0.y);
                    ffma2(acc[i][2], a2, p1.x);
                    ffma2(acc[i][3], a2, p1.y);
                }
            }
        }
        __syncthreads();
    }

#pragma unroll
    for (int i = 0; i < 4; i++) {
        int r = r0 + ty * 4 + i;
#pragma unroll
        for (int gj = 0; gj < 2; gj++) {
            int c = c0 + gj * 64 + tx * 4;
            float2 u0 = unpk2(acc[i][gj * 2 + 0]);
            float2 u1 = unpk2(acc[i][gj * 2 + 1]);
            float4 v;
            v.x = u0.x; v.y = u0.y; v.z = u1.x; v.w = u1.y;
            *(float4*)&dst[(size_t)r * kD + c] = v;
        }
    }
}

// ---------------------------------------------------------------------------
// Kernel 3b: out = sum of 4 partials + b0
// ---------------------------------------------------------------------------
__global__ __launch_bounds__(256)
void out_combine(const float* __restrict__ b0, float* __restrict__ out)
{
    int i4 = blockIdx.x * 256 + threadIdx.x;     // float4 index, 262144 total
    float4 a = *(const float4*)&g_part4[0][(size_t)i4 * 4];
    float4 b = *(const float4*)&g_part4[1][(size_t)i4 * 4];
    float4 c = *(const float4*)&g_part4[2][(size_t)i4 * 4];
    float4 d = *(const float4*)&g_part4[3][(size_t)i4 * 4];
    float4 bb = *(const float4*)&b0[(i4 & 63) * 4];
    float4 v;
    v.x = a.x + b.x + c.x + d.x + bb.x;
    v.y = a.y + b.y + c.y + d.y + bb.y;
    v.z = a.z + b.z + c.z + d.z + bb.z;
    v.w = a.w + b.w + c.w + d.w + bb.w;
    *(float4*)&out[(size_t)i4 * 4] = v;
}

// ---------------------------------------------------------------------------
extern "C" void kernel_launch(void* const* d_in, const int* in_sizes, int n_in,
                              void* d_out, int out_size)
{
    const float *x = nullptr, *Wqkv = nullptr, *bqkv = nullptr,
                *W0 = nullptr, *b0 = nullptr;
    for (int i = 0; i < n_in; i++) {
        switch (in_sizes[i]) {
            case kRows * kD: x    = (const float*)d_in[i]; break;
            case kD * kC3:   Wqkv = (const float*)d_in[i]; break;
            case kC3:        bqkv = (const float*)d_in[i]; break;
            case kDH * kD:   W0   = (const float*)d_in[i]; break;
            case kD:         b0   = (const float*)d_in[i]; break;
            default: break;
        }
    }
    float* out = (float*)d_out;

    const size_t smem1 = (size_t)(2 * 2304 + 2 * 4224) * sizeof(float);             // 52224
    const size_t smem2 = (size_t)(2 * 2304 + 2 * 4224 + 2048 + 128) * sizeof(float); // 60928
    const size_t smem3 = (size_t)(2 * 2304 + 2 * 4224 + 512) * sizeof(float);       // 54272
    static bool attr_done = false;
    if (!attr_done) {
        cudaFuncSetAttribute(qkv_gemm_kernel,
                             cudaFuncAttributeMaxDynamicSharedMemorySize, (int)smem1);
        cudaFuncSetAttribute(score_diag_kernel,
                             cudaFuncAttributeMaxDynamicSharedMemorySize, (int)smem2);
        cudaFuncSetAttribute(out_gemm_kernel,
                             cudaFuncAttributeMaxDynamicSharedMemorySize, (int)smem3);
        attr_done = true;
    }

    qkv_gemm_kernel<<<dim3(kC3 / 128, kRows / 64), 256, smem1>>>(x, Wqkv, bqkv);
    transpose_qk_kernel<<<2048, 256>>>();
    score_diag_kernel<<<dim3(kN / 128, kB * kH), 256, smem2>>>();
    out_gemm_kernel<<<dim3(kD / 128, kRows / 64, 4), 256, smem3>>>(W0);
    out_combine<<<1024, 256>>>(b0, out);
}

// round 11
// speedup vs baseline: 1.0503x; 1.0503x over previous
#include <cuda_runtime.h>
#include <cstdint>

// Problem constants
constexpr int kB = 4;
constexpr int kN = 1024;
constexpr int kD = 256;
constexpr int kH = 8;
constexpr int kDH  = kD * kH;          // 2048
constexpr int kNDH = kN * kDH;         // 2097152
constexpr int kSeg = kB * kNDH;        // 8388608  (q/k/v segment, floats)
constexpr int kC3  = 3 * kDH;          // 6144
constexpr int kRows = kB * kN;         // 4096

// Scratch (device globals; no dynamic allocation allowed)
__device__ float g_qkv[3ull * kSeg];   // ~100.7 MB : QKV in reference flat layout
__device__ float g_qkT[2ull * kSeg];   // seg0: Q n-major scaled [bh][n][d]
                                       // seg1: K d-major       [bh][d][n]
__device__ float g_diag[kRows * kH];
__device__ float g_part4[4][kRows * kD];  // k3 K-split partials

// ---------------- cp.async helpers ----------------
__device__ __forceinline__ void cp16(void* smem_dst, const void* gmem_src) {
    unsigned s = (unsigned)__cvta_generic_to_shared(smem_dst);
    asm volatile("cp.async.cg.shared.global [%0], [%1], 16;\n" :: "r"(s), "l"(gmem_src));
}
__device__ __forceinline__ void cp_commit() {
    asm volatile("cp.async.commit_group;\n");
}
template <int N>
__device__ __forceinline__ void cp_wait() {
    asm volatile("cp.async.wait_group %0;\n" :: "n"(N));
}

// ---------------- packed f32x2 helpers (Blackwell FFMA2) ----------------
__device__ __forceinline__ void ffma2(uint64_t& d, uint64_t a, uint64_t b) {
    asm("fma.rn.f32x2 %0, %1, %2, %0;" : "+l"(d) : "l"(a), "l"(b));
}
__device__ __forceinline__ uint64_t bcast2(float x) {
    uint64_t r;
    asm("mov.b64 %0, {%1, %1};" : "=l"(r) : "r"(__float_as_uint(x)));
    return r;
}
__device__ __forceinline__ float2 unpk2(uint64_t v) {
    uint32_t lo, hi;
    asm("mov.b64 {%0, %1}, %2;" : "=r"(lo), "=r"(hi) : "l"(v));
    return make_float2(__uint_as_float(lo), __uint_as_float(hi));
}
__device__ __forceinline__ float selc(float4 v, int kk) {
    return (kk == 0) ? v.x : (kk == 1) ? v.y : (kk == 2) ? v.z : v.w;
}

// Shared inner-loop: one 32-k chunk of a 128x128 tile.
// A_ m-major [128][36]; B_ k-major [32][132].
// Thread owns rows (wm*64 + r*8 + rowg), cols (wn*32 + colg*8 + 0..7).
__device__ __forceinline__ void mma_chunk(const float* __restrict__ A_,
                                          const float* __restrict__ B_,
                                          uint64_t (&acc)[8][4],
                                          int wm, int wn, int rowg, int colg)
{
#pragma unroll
    for (int kg = 0; kg < 32; kg += 4) {
        float4 av[8];
#pragma unroll
        for (int r = 0; r < 8; r++)
            av[r] = *(const float4*)&A_[(wm * 64 + r * 8 + rowg) * 36 + kg];
#pragma unroll
        for (int kk = 0; kk < 4; kk++) {
            const float* brow = &B_[(kg + kk) * 132 + wn * 32 + colg * 8];
            ulonglong2 q0 = *(const ulonglong2*)brow;
            ulonglong2 q1 = *(const ulonglong2*)(brow + 4);
#pragma unroll
            for (int r = 0; r < 8; r++) {
                uint64_t a2 = bcast2(selc(av[r], kk));
                ffma2(acc[r][0], a2, q0.x);
                ffma2(acc[r][1], a2, q0.y);
                ffma2(acc[r][2], a2, q1.x);
                ffma2(acc[r][3], a2, q1.y);
            }
        }
    }
}

// ---------------------------------------------------------------------------
// Kernel 1: QKV = x @ Wqkv + bqkv     [4096,256] @ [256,6144]
// CTA 128x128, warp 64x32, thread 8x8 packed. grid(48, 32).
// ---------------------------------------------------------------------------
__global__ __launch_bounds__(256, 2)
void qkv_gemm_kernel(const float* __restrict__ x,
                     const float* __restrict__ W,
                     const float* __restrict__ bias)
{
    extern __shared__ float sm[];
    float* As = sm;                 // [2][128*36]
    float* Bs = sm + 2 * 4608;      // [2][32*132]

    const int t = threadIdx.x, lane = t & 31, w = t >> 5;
    const int wm = w & 1, wn = w >> 1;
    const int rowg = lane >> 2, colg = lane & 3;
    const int r0 = blockIdx.y * 128, c0 = blockIdx.x * 128;

    const int ar = t >> 3, ap = t & 7;    // A loader: rows ar+32j, part ap
    const int bp = t & 31, br = t >> 5;   // B loader: part bp, k rows br+8i

    uint64_t acc[8][4] = {};

#pragma unroll
    for (int j = 0; j < 4; j++) {
        int m = ar + 32 * j;
        cp16(&As[m * 36 + ap * 4], &x[(size_t)(r0 + m) * kD + ap * 4]);
    }
#pragma unroll
    for (int i = 0; i < 4; i++) {
        int k = br + 8 * i;
        cp16(&Bs[k * 132 + bp * 4], &W[(size_t)k * kC3 + c0 + bp * 4]);
    }
    cp_commit();

    for (int c = 0; c < 8; c++) {
        const int buf = c & 1;
        if (c < 7) {
            const int kc = (c + 1) * 32;
            const int nb = buf ^ 1;
#pragma unroll
            for (int j = 0; j < 4; j++) {
                int m = ar + 32 * j;
                cp16(&As[nb * 4608 + m * 36 + ap * 4],
                     &x[(size_t)(r0 + m) * kD + kc + ap * 4]);
            }
#pragma unroll
            for (int i = 0; i < 4; i++) {
                int k = br + 8 * i;
                cp16(&Bs[nb * 4224 + k * 132 + bp * 4],
                     &W[(size_t)(kc + k) * kC3 + c0 + bp * 4]);
            }
            cp_commit();
            cp_wait<1>();
        } else {
            cp_wait<0>();
        }
        __syncthreads();
        mma_chunk(&As[buf * 4608], &Bs[buf * 4224], acc, wm, wn, rowg, colg);
        __syncthreads();
    }

    const int cbase = c0 + wn * 32 + colg * 8;
#pragma unroll
    for (int r = 0; r < 8; r++) {
        int row = r0 + wm * 64 + r * 8 + rowg;
        float2 u0 = unpk2(acc[r][0]), u1 = unpk2(acc[r][1]);
        float2 u2 = unpk2(acc[r][2]), u3 = unpk2(acc[r][3]);
        float4 v0, v1;
        v0.x = u0.x + bias[cbase + 0]; v0.y = u0.y + bias[cbase + 1];
        v0.z = u1.x + bias[cbase + 2]; v0.w = u1.y + bias[cbase + 3];
        v1.x = u2.x + bias[cbase + 4]; v1.y = u2.y + bias[cbase + 5];
        v1.z = u3.x + bias[cbase + 6]; v1.w = u3.y + bias[cbase + 7];
        *(float4*)&g_qkv[(size_t)row * kC3 + cbase] = v0;
        *(float4*)&g_qkv[(size_t)row * kC3 + cbase + 4] = v1;
    }
}

// ---------------------------------------------------------------------------
// Transpose: q -> [bh][n][d] (scaled 1/16);  k -> [bh][d][n] (d-major).
// (round-10 proven version, verbatim)
// ---------------------------------------------------------------------------
__global__ __launch_bounds__(256)
void transpose_qk_kernel()
{
    __shared__ float smt[8][32][33];   // [h][qd][n]
    const int bid = blockIdx.x;
    const int qb  = bid & 7;
    const int nb  = (bid >> 3) & 31;
    const int b   = (bid >> 8) & 3;
    const int seg = bid >> 10;
    const int t   = threadIdx.x;

    const float* src = g_qkv + (size_t)seg * kSeg + (size_t)b * kNDH
                     + (size_t)(nb * 32) * kDH + qb * 32 * 8;
    {
        const int nl = t >> 3, f = t & 7;
        const int h0 = (f & 1) * 4, q0 = f >> 1;
#pragma unroll
        for (int i = 0; i < 8; i++) {
            float4 v = *(const float4*)&src[(size_t)nl * kDH + (f + i * 8) * 4];
            int ql = q0 + i * 4;
            smt[h0 + 0][ql][nl] = v.x;
            smt[h0 + 1][ql][nl] = v.y;
            smt[h0 + 2][ql][nl] = v.z;
            smt[h0 + 3][ql][nl] = v.w;
        }
    }
    __syncthreads();
    if (seg == 0) {
        const int q4 = (t & 7) * 4, hn = t >> 3;
#pragma unroll
        for (int i = 0; i < 8; i++) {
            int idx = hn + i * 32;
            int h = idx >> 5, n = idx & 31;
            float4 v;
            v.x = smt[h][q4 + 0][n] * 0.0625f;
            v.y = smt[h][q4 + 1][n] * 0.0625f;
            v.z = smt[h][q4 + 2][n] * 0.0625f;
            v.w = smt[h][q4 + 3][n] * 0.0625f;
            float* dst = g_qkT
                       + (((size_t)(b * 8 + h) * kN + nb * 32 + n) * kD)
                       + qb * 32 + q4;
            *(float4*)dst = v;
        }
    } else {
#pragma unroll
        for (int i = 0; i < 8; i++) {
            int idx = t + i * 256;
            int h = idx >> 8, rem = idx & 255;
            int q = rem >> 3, nf = rem & 7;
            float4 v;
            v.x = smt[h][q][nf * 4 + 0];
            v.y = smt[h][q][nf * 4 + 1];
            v.z = smt[h][q][nf * 4 + 2];
            v.w = smt[h][q][nf * 4 + 3];
            float* dst = g_qkT + (size_t)kSeg
                       + (((size_t)(b * 8 + h) * kD + qb * 32 + q) * kN)
                       + nb * 32 + nf * 4;
            *(float4*)dst = v;
        }
    }
}

// ---------------------------------------------------------------------------
// Kernel 2: per (b,h): S[m,n] = qs_m . k_n; column softmax over m (no max
// pass: |S| <~ 1); keep diagonal attn. CTA: 128 n-cols, m in 8 tiles of 128.
// Warp 64x32, thread 8x8 packed. grid(8, 32).
// ---------------------------------------------------------------------------
__global__ __launch_bounds__(256, 2)
void score_diag_kernel()
{
    extern __shared__ float sm[];
    float* As     = sm;                        // [2][128*36]
    float* Ks     = sm + 2 * 4608;             // [2][32*132]
    float* red    = sm + 2 * 4608 + 2 * 4224;  // [16*128]
    float* diagsm = red + 2048;                // [128]

    const int t = threadIdx.x, lane = t & 31, w = t >> 5;
    const int wm = w & 1, wn = w >> 1;
    const int rowg = lane >> 2, colg = lane & 3;
    const int bh = blockIdx.y;
    const int b  = bh >> 3, h = bh & 7;
    const int n0 = blockIdx.x * 128;

    const float* Q  = g_qkT + (size_t)bh * (kN * kD);                 // [n][d]
    const float* Kd = g_qkT + (size_t)kSeg + (size_t)bh * (kD * kN);  // [d][n]

    const int ar = t >> 3, ap = t & 7;
    const int bp = t & 31, br = t >> 5;

    float colsum[8];
#pragma unroll
    for (int j = 0; j < 8; j++) colsum[j] = 0.f;

    for (int mt = 0; mt < 8; mt++) {
        const int m0 = mt * 128;
        uint64_t acc[8][4] = {};

#pragma unroll
        for (int j = 0; j < 4; j++) {
            int m = ar + 32 * j;
            cp16(&As[m * 36 + ap * 4], &Q[(size_t)(m0 + m) * kD + ap * 4]);
        }
#pragma unroll
        for (int i = 0; i < 4; i++) {
            int k = br + 8 * i;
            cp16(&Ks[k * 132 + bp * 4], &Kd[(size_t)k * kN + n0 + bp * 4]);
        }
        cp_commit();

        for (int c = 0; c < 8; c++) {
            const int buf = c & 1;
            if (c < 7) {
                const int kc = (c + 1) * 32;
                const int nb = buf ^ 1;
#pragma unroll
                for (int j = 0; j < 4; j++) {
                    int m = ar + 32 * j;
                    cp16(&As[nb * 4608 + m * 36 + ap * 4],
                         &Q[(size_t)(m0 + m) * kD + kc + ap * 4]);
                }
#pragma unroll
                for (int i = 0; i < 4; i++) {
                    int k = br + 8 * i;
                    cp16(&Ks[nb * 4224 + k * 132 + bp * 4],
                         &Kd[(size_t)(kc + k) * kN + n0 + bp * 4]);
                }
                cp_commit();
                cp_wait<1>();
            } else {
                cp_wait<0>();
            }
            __syncthreads();
            mma_chunk(&As[buf * 4608], &Ks[buf * 4224], acc, wm, wn, rowg, colg);
            __syncthreads();
        }

        // ---- epilogue: exp + colsum (registers); diagonal -> smem ----
        const bool diagtile = (mt == (int)blockIdx.x);
        const int clb = wn * 32 + colg * 8;     // local col base
#pragma unroll
        for (int jp = 0; jp < 4; jp++) {
            float s0 = 0.f, s1 = 0.f;
#pragma unroll
            for (int r = 0; r < 8; r++) {
                float2 u = unpk2(acc[r][jp]);
                float e0 = __expf(u.x), e1 = __expf(u.y);
                s0 += e0; s1 += e1;
                if (diagtile) {
                    int lm = wm * 64 + r * 8 + rowg;     // local row == local col?
                    if (lm == clb + 2 * jp)     diagsm[clb + 2 * jp]     = e0;
                    if (lm == clb + 2 * jp + 1) diagsm[clb + 2 * jp + 1] = e1;
                }
            }
            colsum[2 * jp]     += s0;
            colsum[2 * jp + 1] += s1;
        }
    }

    // ---- single final reduction across the 16 (wm,rowg) slots ----
    const int slot = wm * 8 + rowg;
    const int clb = wn * 32 + colg * 8;
#pragma unroll
    for (int j = 0; j < 8; j++)
        red[slot * 128 + clb + j] = colsum[j];
    __syncthreads();
    if (t < 128) {
        float total = red[t];
#pragma unroll
        for (int r = 1; r < 16; r++) total += red[r * 128 + t];
        g_diag[((size_t)b * kN + (n0 + t)) * kH + h] = diagsm[t] / total;
    }
}

// ---------------------------------------------------------------------------
// Kernel 3: partial = (diag .* v) @ W0, K-split 4.  [4096,2048]@[2048,256]
// CTA 128m x 128n over 512-wide K slice; A fused diag multiply via LDG+STS.
// grid(2 ctiles, 32 mtiles, 4 ksplit) = 256 CTAs.
// ---------------------------------------------------------------------------
__global__ __launch_bounds__(256, 2)
void out_gemm_kernel(const float* __restrict__ W0)
{
    extern __shared__ float sm[];
    float* As  = sm;                        // [2][128*36]
    float* Ws  = sm + 2 * 4608;             // [2][32*132]
    float* dsm = sm + 2 * 4608 + 2 * 4224;  // [128*8]

    const int t = threadIdx.x, lane = t & 31, w = t >> 5;
    const int wm = w & 1, wn = w >> 1;
    const int rowg = lane >> 2, colg = lane & 3;
    const int c0 = blockIdx.x * 128;
    const int r0 = blockIdx.y * 128;
    const int kb = blockIdx.z * 512;
    const float* vseg = g_qkv + 2ull * kSeg;
    float* dst = g_part4[blockIdx.z];

    for (int idx = t; idx < 1024; idx += 256)
        dsm[idx] = g_diag[(size_t)(r0 + (idx >> 3)) * kH + (idx & 7)];

    const int ar = t >> 3, ap = t & 7;
    const int bp = t & 31, br = t >> 5;

    uint64_t acc[8][4] = {};

    // preload chunk 0
    float4 areg[4];
#pragma unroll
    for (int i = 0; i < 4; i++) {
        int k = br + 8 * i;
        cp16(&Ws[k * 132 + bp * 4], &W0[(size_t)(kb + k) * kD + c0 + bp * 4]);
    }
    cp_commit();
#pragma unroll
    for (int j = 0; j < 4; j++) {
        int m = ar + 32 * j;
        areg[j] = *(const float4*)&vseg[(size_t)(r0 + m) * kDH + kb + ap * 4];
    }
    __syncthreads();   // dsm ready

    for (int c = 0; c < 16; c++) {
        const int buf = c & 1;
        {
            const int hoff = (ap * 4) & 7;   // head offset of this float4 (0 or 4)
#pragma unroll
            for (int j = 0; j < 4; j++) {
                int m = ar + 32 * j;
                float4 dv = *(const float4*)&dsm[m * 8 + hoff];
                float4 v = areg[j];
                v.x *= dv.x; v.y *= dv.y; v.z *= dv.z; v.w *= dv.w;
                *(float4*)&As[buf * 4608 + m * 36 + ap * 4] = v;
            }
        }
        if (c < 15) {
            const int kc = (c + 1) * 32;
#pragma unroll
            for (int i = 0; i < 4; i++) {
                int k = br + 8 * i;
                cp16(&Ws[(buf ^ 1) * 4224 + k * 132 + bp * 4],
                     &W0[(size_t)(kb + kc + k) * kD + c0 + bp * 4]);
            }
            cp_commit();
#pragma unroll
            for (int j = 0; j < 4; j++) {
                int m = ar + 32 * j;
                areg[j] = *(const float4*)
                    &vseg[(size_t)(r0 + m) * kDH + kb + kc + ap * 4];
            }
            cp_wait<1>();
        } else {
            cp_wait<0>();
        }
        __syncthreads();
        mma_chunk(&As[buf * 4608], &Ws[buf * 4224], acc, wm, wn, rowg, colg);
        __syncthreads();
    }

    const int cbase = c0 + wn * 32 + colg * 8;
#pragma unroll
    for (int r = 0; r < 8; r++) {
        int row = r0 + wm * 64 + r * 8 + rowg;
        float2 u0 = unpk2(acc[r][0]), u1 = unpk2(acc[r][1]);
        float2 u2 = unpk2(acc[r][2]), u3 = unpk2(acc[r][3]);
        float4 v0 = {u0.x, u0.y, u1.x, u1.y};
        float4 v1 = {u2.x, u2.y, u3.x, u3.y};
        *(float4*)&dst[(size_t)row * kD + cbase] = v0;
        *(float4*)&dst[(size_t)row * kD + cbase + 4] = v1;
    }
}

// ---------------------------------------------------------------------------
// Kernel 3b: out = sum of 4 partials + b0
// ---------------------------------------------------------------------------
__global__ __launch_bounds__(256)
void out_combine(const float* __restrict__ b0, float* __restrict__ out)
{
    int i4 = blockIdx.x * 256 + threadIdx.x;     // float4 index, 262144 total
    float4 a = *(const float4*)&g_part4[0][(size_t)i4 * 4];
    float4 b = *(const float4*)&g_part4[1][(size_t)i4 * 4];
    float4 c = *(const float4*)&g_part4[2][(size_t)i4 * 4];
    float4 d = *(const float4*)&g_part4[3][(size_t)i4 * 4];
    float4 bb = *(const float4*)&b0[(i4 & 63) * 4];
    float4 v;
    v.x = a.x + b.x + c.x + d.x + bb.x;
    v.y = a.y + b.y + c.y + d.y + bb.y;
    v.z = a.z + b.z + c.z + d.z + bb.z;
    v.w = a.w + b.w + c.w + d.w + bb.w;
    *(float4*)&out[(size_t)i4 * 4] = v;
}

// ---------------------------------------------------------------------------
extern "C" void kernel_launch(void* const* d_in, const int* in_sizes, int n_in,
                              void* d_out, int out_size)
{
    const float *x = nullptr, *Wqkv = nullptr, *bqkv = nullptr,
                *W0 = nullptr, *b0 = nullptr;
    for (int i = 0; i < n_in; i++) {
        switch (in_sizes[i]) {
            case kRows * kD: x    = (const float*)d_in[i]; break;
            case kD * kC3:   Wqkv = (const float*)d_in[i]; break;
            case kC3:        bqkv = (const float*)d_in[i]; break;
            case kDH * kD:   W0   = (const float*)d_in[i]; break;
            case kD:         b0   = (const float*)d_in[i]; break;
            default: break;
        }
    }
    float* out = (float*)d_out;

    const size_t smem1 = (size_t)(2 * 4608 + 2 * 4224) * sizeof(float);              // 70656
    const size_t smem2 = (size_t)(2 * 4608 + 2 * 4224 + 2048 + 128) * sizeof(float); // 79360
    const size_t smem3 = (size_t)(2 * 4608 + 2 * 4224 + 1024) * sizeof(float);       // 74752
    static bool attr_done = false;
    if (!attr_done) {
        cudaFuncSetAttribute(qkv_gemm_kernel,
                             cudaFuncAttributeMaxDynamicSharedMemorySize, (int)smem1);
        cudaFuncSetAttribute(score_diag_kernel,
                             cudaFuncAttributeMaxDynamicSharedMemorySize, (int)smem2);
        cudaFuncSetAttribute(out_gemm_kernel,
                             cudaFuncAttributeMaxDynamicSharedMemorySize, (int)smem3);
        attr_done = true;
    }

    qkv_gemm_kernel<<<dim3(kC3 / 128, kRows / 128), 256, smem1>>>(x, Wqkv, bqkv);
    transpose_qk_kernel<<<2048, 256>>>();
    score_diag_kernel<<<dim3(kN / 128, kB * kH), 256, smem2>>>();
    out_gemm_kernel<<<dim3(kD / 128, kRows / 128, 4), 256, smem3>>>(W0);
    out_combine<<<1024, 256>>>(b0, out);
}

// round 12
// speedup vs baseline: 1.1130x; 1.0596x over previous
#include <cuda_runtime.h>
#include <cstdint>

// Problem constants
constexpr int kB = 4;
constexpr int kN = 1024;
constexpr int kD = 256;
constexpr int kH = 8;
constexpr int kDH  = kD * kH;          // 2048
constexpr int kNDH = kN * kDH;         // 2097152
constexpr int kSeg = kB * kNDH;        // 8388608  (q/k/v segment, floats)
constexpr int kC3  = 3 * kDH;          // 6144
constexpr int kRows = kB * kN;         // 4096

// Scratch (device globals; no dynamic allocation allowed)
__device__ float g_qkv[3ull * kSeg];   // ~100.7 MB : QKV in reference flat layout
__device__ float g_qkT[2ull * kSeg];   // seg0: Q n-major scaled [bh][n][d]
                                       // seg1: K d-major       [bh][d][n]
__device__ float g_diag[kRows * kH];
__device__ float g_pcs[4 * 32 * kN];      // k2 partial colsums [z][bh][n]
__device__ float g_diagexp[32 * kN];      // exp(S[n,n]) per [bh][n]
__device__ float g_part8[8][kRows * kD];  // k3 K-split partials (32 MB)

// ---------------- cp.async helpers ----------------
__device__ __forceinline__ void cp16(void* smem_dst, const void* gmem_src) {
    unsigned s = (unsigned)__cvta_generic_to_shared(smem_dst);
    asm volatile("cp.async.cg.shared.global [%0], [%1], 16;\n" :: "r"(s), "l"(gmem_src));
}
__device__ __forceinline__ void cp_commit() {
    asm volatile("cp.async.commit_group;\n");
}
template <int N>
__device__ __forceinline__ void cp_wait() {
    asm volatile("cp.async.wait_group %0;\n" :: "n"(N));
}

// ---------------- packed f32x2 helpers (Blackwell FFMA2) ----------------
__device__ __forceinline__ void ffma2(uint64_t& d, uint64_t a, uint64_t b) {
    asm("fma.rn.f32x2 %0, %1, %2, %0;" : "+l"(d) : "l"(a), "l"(b));
}
__device__ __forceinline__ uint64_t bcast2(float x) {
    uint64_t r;
    asm("mov.b64 %0, {%1, %1};" : "=l"(r) : "r"(__float_as_uint(x)));
    return r;
}
__device__ __forceinline__ float2 unpk2(uint64_t v) {
    uint32_t lo, hi;
    asm("mov.b64 {%0, %1}, %2;" : "=r"(lo), "=r"(hi) : "l"(v));
    return make_float2(__uint_as_float(lo), __uint_as_float(hi));
}
__device__ __forceinline__ float selc(float4 v, int kk) {
    return (kk == 0) ? v.x : (kk == 1) ? v.y : (kk == 2) ? v.z : v.w;
}

// Shared inner-loop: one 32-k chunk of a 128x128 tile.
// A_ m-major [128][36]; B_ k-major [32][132].
// Thread owns rows (wm*64 + r*8 + rowg), cols (wn*32 + colg*8 + 0..7).
__device__ __forceinline__ void mma_chunk(const float* __restrict__ A_,
                                          const float* __restrict__ B_,
                                          uint64_t (&acc)[8][4],
                                          int wm, int wn, int rowg, int colg)
{
#pragma unroll
    for (int kg = 0; kg < 32; kg += 4) {
        float4 av[8];
#pragma unroll
        for (int r = 0; r < 8; r++)
            av[r] = *(const float4*)&A_[(wm * 64 + r * 8 + rowg) * 36 + kg];
#pragma unroll
        for (int kk = 0; kk < 4; kk++) {
            const float* brow = &B_[(kg + kk) * 132 + wn * 32 + colg * 8];
            ulonglong2 q0 = *(const ulonglong2*)brow;
            ulonglong2 q1 = *(const ulonglong2*)(brow + 4);
#pragma unroll
            for (int r = 0; r < 8; r++) {
                uint64_t a2 = bcast2(selc(av[r], kk));
                ffma2(acc[r][0], a2, q0.x);
                ffma2(acc[r][1], a2, q0.y);
                ffma2(acc[r][2], a2, q1.x);
                ffma2(acc[r][3], a2, q1.y);
            }
        }
    }
}

// ---------------------------------------------------------------------------
// Kernel 1: QKV = x @ Wqkv + bqkv     [4096,256] @ [256,6144]
// CTA 128x128, warp 64x32, thread 8x8 packed. grid(48, 32) = 1536 CTAs.
// (round-11 proven version, verbatim)
// ---------------------------------------------------------------------------
__global__ __launch_bounds__(256, 2)
void qkv_gemm_kernel(const float* __restrict__ x,
                     const float* __restrict__ W,
                     const float* __restrict__ bias)
{
    extern __shared__ float sm[];
    float* As = sm;                 // [2][128*36]
    float* Bs = sm + 2 * 4608;      // [2][32*132]

    const int t = threadIdx.x, lane = t & 31, w = t >> 5;
    const int wm = w & 1, wn = w >> 1;
    const int rowg = lane >> 2, colg = lane & 3;
    const int r0 = blockIdx.y * 128, c0 = blockIdx.x * 128;

    const int ar = t >> 3, ap = t & 7;
    const int bp = t & 31, br = t >> 5;

    uint64_t acc[8][4] = {};

#pragma unroll
    for (int j = 0; j < 4; j++) {
        int m = ar + 32 * j;
        cp16(&As[m * 36 + ap * 4], &x[(size_t)(r0 + m) * kD + ap * 4]);
    }
#pragma unroll
    for (int i = 0; i < 4; i++) {
        int k = br + 8 * i;
        cp16(&Bs[k * 132 + bp * 4], &W[(size_t)k * kC3 + c0 + bp * 4]);
    }
    cp_commit();

    for (int c = 0; c < 8; c++) {
        const int buf = c & 1;
        if (c < 7) {
            const int kc = (c + 1) * 32;
            const int nb = buf ^ 1;
#pragma unroll
            for (int j = 0; j < 4; j++) {
                int m = ar + 32 * j;
                cp16(&As[nb * 4608 + m * 36 + ap * 4],
                     &x[(size_t)(r0 + m) * kD + kc + ap * 4]);
            }
#pragma unroll
            for (int i = 0; i < 4; i++) {
                int k = br + 8 * i;
                cp16(&Bs[nb * 4224 + k * 132 + bp * 4],
                     &W[(size_t)(kc + k) * kC3 + c0 + bp * 4]);
            }
            cp_commit();
            cp_wait<1>();
        } else {
            cp_wait<0>();
        }
        __syncthreads();
        mma_chunk(&As[buf * 4608], &Bs[buf * 4224], acc, wm, wn, rowg, colg);
        __syncthreads();
    }

    const int cbase = c0 + wn * 32 + colg * 8;
#pragma unroll
    for (int r = 0; r < 8; r++) {
        int row = r0 + wm * 64 + r * 8 + rowg;
        float2 u0 = unpk2(acc[r][0]), u1 = unpk2(acc[r][1]);
        float2 u2 = unpk2(acc[r][2]), u3 = unpk2(acc[r][3]);
        float4 v0, v1;
        v0.x = u0.x + bias[cbase + 0]; v0.y = u0.y + bias[cbase + 1];
        v0.z = u1.x + bias[cbase + 2]; v0.w = u1.y + bias[cbase + 3];
        v1.x = u2.x + bias[cbase + 4]; v1.y = u2.y + bias[cbase + 5];
        v1.z = u3.x + bias[cbase + 6]; v1.w = u3.y + bias[cbase + 7];
        *(float4*)&g_qkv[(size_t)row * kC3 + cbase] = v0;
        *(float4*)&g_qkv[(size_t)row * kC3 + cbase + 4] = v1;
    }
}

// ---------------------------------------------------------------------------
// Transpose: q -> [bh][n][d] (scaled 1/16);  k -> [bh][d][n] (d-major).
// (round-10/11 proven version, verbatim)
// ---------------------------------------------------------------------------
__global__ __launch_bounds__(256)
void transpose_qk_kernel()
{
    __shared__ float smt[8][32][33];   // [h][qd][n]
    const int bid = blockIdx.x;
    const int qb  = bid & 7;
    const int nb  = (bid >> 3) & 31;
    const int b   = (bid >> 8) & 3;
    const int seg = bid >> 10;
    const int t   = threadIdx.x;

    const float* src = g_qkv + (size_t)seg * kSeg + (size_t)b * kNDH
                     + (size_t)(nb * 32) * kDH + qb * 32 * 8;
    {
        const int nl = t >> 3, f = t & 7;
        const int h0 = (f & 1) * 4, q0 = f >> 1;
#pragma unroll
        for (int i = 0; i < 8; i++) {
            float4 v = *(const float4*)&src[(size_t)nl * kDH + (f + i * 8) * 4];
            int ql = q0 + i * 4;
            smt[h0 + 0][ql][nl] = v.x;
            smt[h0 + 1][ql][nl] = v.y;
            smt[h0 + 2][ql][nl] = v.z;
            smt[h0 + 3][ql][nl] = v.w;
        }
    }
    __syncthreads();
    if (seg == 0) {
        const int q4 = (t & 7) * 4, hn = t >> 3;
#pragma unroll
        for (int i = 0; i < 8; i++) {
            int idx = hn + i * 32;
            int h = idx >> 5, n = idx & 31;
            float4 v;
            v.x = smt[h][q4 + 0][n] * 0.0625f;
            v.y = smt[h][q4 + 1][n] * 0.0625f;
            v.z = smt[h][q4 + 2][n] * 0.0625f;
            v.w = smt[h][q4 + 3][n] * 0.0625f;
            float* dst = g_qkT
                       + (((size_t)(b * 8 + h) * kN + nb * 32 + n) * kD)
                       + qb * 32 + q4;
            *(float4*)dst = v;
        }
    } else {
#pragma unroll
        for (int i = 0; i < 8; i++) {
            int idx = t + i * 256;
            int h = idx >> 8, rem = idx & 255;
            int q = rem >> 3, nf = rem & 7;
            float4 v;
            v.x = smt[h][q][nf * 4 + 0];
            v.y = smt[h][q][nf * 4 + 1];
            v.z = smt[h][q][nf * 4 + 2];
            v.w = smt[h][q][nf * 4 + 3];
            float* dst = g_qkT + (size_t)kSeg
                       + (((size_t)(b * 8 + h) * kD + qb * 32 + q) * kN)
                       + nb * 32 + nf * 4;
            *(float4*)dst = v;
        }
    }
}

// ---------------------------------------------------------------------------
// Kernel 2: per (b,h,msplit): partial colsums of exp(S) over 2 m-tiles of 128,
// plus diag-exp when owned. CTA: 128 n-cols. grid(8, 32, 4) = 1024 CTAs.
// ---------------------------------------------------------------------------
__global__ __launch_bounds__(256, 2)
void score_diag_kernel()
{
    extern __shared__ float sm[];
    float* As     = sm;                        // [2][128*36]
    float* Ks     = sm + 2 * 4608;             // [2][32*132]
    float* red    = sm + 2 * 4608 + 2 * 4224;  // [16*128]
    float* diagsm = red + 2048;                // [128]

    const int t = threadIdx.x, lane = t & 31, w = t >> 5;
    const int wm = w & 1, wn = w >> 1;
    const int rowg = lane >> 2, colg = lane & 3;
    const int bh = blockIdx.y;
    const int n0 = blockIdx.x * 128;
    const int z  = blockIdx.z;                 // m-split 0..3

    const float* Q  = g_qkT + (size_t)bh * (kN * kD);                 // [n][d]
    const float* Kd = g_qkT + (size_t)kSeg + (size_t)bh * (kD * kN);  // [d][n]

    const int ar = t >> 3, ap = t & 7;
    const int bp = t & 31, br = t >> 5;

    float colsum[8];
#pragma unroll
    for (int j = 0; j < 8; j++) colsum[j] = 0.f;

    const bool owner = ((int)blockIdx.x >> 1) == z;

    for (int mt = 2 * z; mt < 2 * z + 2; mt++) {
        const int m0 = mt * 128;
        uint64_t acc[8][4] = {};

#pragma unroll
        for (int j = 0; j < 4; j++) {
            int m = ar + 32 * j;
            cp16(&As[m * 36 + ap * 4], &Q[(size_t)(m0 + m) * kD + ap * 4]);
        }
#pragma unroll
        for (int i = 0; i < 4; i++) {
            int k = br + 8 * i;
            cp16(&Ks[k * 132 + bp * 4], &Kd[(size_t)k * kN + n0 + bp * 4]);
        }
        cp_commit();

        for (int c = 0; c < 8; c++) {
            const int buf = c & 1;
            if (c < 7) {
                const int kc = (c + 1) * 32;
                const int nb = buf ^ 1;
#pragma unroll
                for (int j = 0; j < 4; j++) {
                    int m = ar + 32 * j;
                    cp16(&As[nb * 4608 + m * 36 + ap * 4],
                         &Q[(size_t)(m0 + m) * kD + kc + ap * 4]);
                }
#pragma unroll
                for (int i = 0; i < 4; i++) {
                    int k = br + 8 * i;
                    cp16(&Ks[nb * 4224 + k * 132 + bp * 4],
                         &Kd[(size_t)(kc + k) * kN + n0 + bp * 4]);
                }
                cp_commit();
                cp_wait<1>();
            } else {
                cp_wait<0>();
            }
            __syncthreads();
            mma_chunk(&As[buf * 4608], &Ks[buf * 4224], acc, wm, wn, rowg, colg);
            __syncthreads();
        }

        // ---- epilogue: exp + colsum (registers); diagonal -> smem ----
        const bool diagtile = (mt == (int)blockIdx.x);
        const int clb = wn * 32 + colg * 8;
#pragma unroll
        for (int jp = 0; jp < 4; jp++) {
            float s0 = 0.f, s1 = 0.f;
#pragma unroll
            for (int r = 0; r < 8; r++) {
                float2 u = unpk2(acc[r][jp]);
                float e0 = __expf(u.x), e1 = __expf(u.y);
                s0 += e0; s1 += e1;
                if (diagtile) {
                    int lm = wm * 64 + r * 8 + rowg;
                    if (lm == clb + 2 * jp)     diagsm[clb + 2 * jp]     = e0;
                    if (lm == clb + 2 * jp + 1) diagsm[clb + 2 * jp + 1] = e1;
                }
            }
            colsum[2 * jp]     += s0;
            colsum[2 * jp + 1] += s1;
        }
    }

    // ---- reduction across the 16 (wm,rowg) slots; write partials ----
    const int slot = wm * 8 + rowg;
    const int clb = wn * 32 + colg * 8;
#pragma unroll
    for (int j = 0; j < 8; j++)
        red[slot * 128 + clb + j] = colsum[j];
    __syncthreads();
    if (t < 128) {
        float total = red[t];
#pragma unroll
        for (int r = 1; r < 16; r++) total += red[r * 128 + t];
        g_pcs[((size_t)z * 32 + bh) * kN + n0 + t] = total;
        if (owner)
            g_diagexp[(size_t)bh * kN + n0 + t] = diagsm[t];
    }
}

// ---------------------------------------------------------------------------
// Kernel 2b: g_diag = diagexp / sum_z pcs
// ---------------------------------------------------------------------------
__global__ __launch_bounds__(256)
void finish_diag()
{
    int id = blockIdx.x * 256 + threadIdx.x;   // 32768 = 32 bh x 1024 n
    int bh = id >> 10, n = id & 1023;
    float tot = g_pcs[(size_t)bh * kN + n]
              + g_pcs[((size_t)32 + bh) * kN + n]
              + g_pcs[((size_t)64 + bh) * kN + n]
              + g_pcs[((size_t)96 + bh) * kN + n];
    int b = bh >> 3, h = bh & 7;
    g_diag[((size_t)b * kN + n) * kH + h] = g_diagexp[(size_t)bh * kN + n] / tot;
}

// ---------------------------------------------------------------------------
// Kernel 3: partial = (diag .* v) @ W0, K-split 8.  [4096,2048]@[2048,256]
// CTA 128m x 128n over 256-wide K slice (8 chunks).
// grid(2 ctiles, 32 mtiles, 8 ksplit) = 1024 CTAs.
// ---------------------------------------------------------------------------
__global__ __launch_bounds__(256, 2)
void out_gemm_kernel(const float* __restrict__ W0)
{
    extern __shared__ float sm[];
    float* As  = sm;                        // [2][128*36]
    float* Ws  = sm + 2 * 4608;             // [2][32*132]
    float* dsm = sm + 2 * 4608 + 2 * 4224;  // [128*8]

    const int t = threadIdx.x, lane = t & 31, w = t >> 5;
    const int wm = w & 1, wn = w >> 1;
    const int rowg = lane >> 2, colg = lane & 3;
    const int c0 = blockIdx.x * 128;
    const int r0 = blockIdx.y * 128;
    const int kb = blockIdx.z * 256;
    const float* vseg = g_qkv + 2ull * kSeg;
    float* dst = g_part8[blockIdx.z];

    for (int idx = t; idx < 1024; idx += 256)
        dsm[idx] = g_diag[(size_t)(r0 + (idx >> 3)) * kH + (idx & 7)];

    const int ar = t >> 3, ap = t & 7;
    const int bp = t & 31, br = t >> 5;

    uint64_t acc[8][4] = {};

    // preload chunk 0
    float4 areg[4];
#pragma unroll
    for (int i = 0; i < 4; i++) {
        int k = br + 8 * i;
        cp16(&Ws[k * 132 + bp * 4], &W0[(size_t)(kb + k) * kD + c0 + bp * 4]);
    }
    cp_commit();
#pragma unroll
    for (int j = 0; j < 4; j++) {
        int m = ar + 32 * j;
        areg[j] = *(const float4*)&vseg[(size_t)(r0 + m) * kDH + kb + ap * 4];
    }
    __syncthreads();   // dsm ready

    for (int c = 0; c < 8; c++) {
        const int buf = c & 1;
        {
            const int hoff = (ap * 4) & 7;   // head offset of this float4 (0 or 4)
#pragma unroll
            for (int j = 0; j < 4; j++) {
                int m = ar + 32 * j;
                float4 dv = *(const float4*)&dsm[m * 8 + hoff];
                float4 v = areg[j];
                v.x *= dv.x; v.y *= dv.y; v.z *= dv.z; v.w *= dv.w;
                *(float4*)&As[buf * 4608 + m * 36 + ap * 4] = v;
            }
        }
        if (c < 7) {
            const int kc = (c + 1) * 32;
#pragma unroll
            for (int i = 0; i < 4; i++) {
                int k = br + 8 * i;
                cp16(&Ws[(buf ^ 1) * 4224 + k * 132 + bp * 4],
                     &W0[(size_t)(kb + kc + k) * kD + c0 + bp * 4]);
            }
            cp_commit();
#pragma unroll
            for (int j = 0; j < 4; j++) {
                int m = ar + 32 * j;
                areg[j] = *(const float4*)
                    &vseg[(size_t)(r0 + m) * kDH + kb + kc + ap * 4];
            }
            cp_wait<1>();
        } else {
            cp_wait<0>();
        }
        __syncthreads();
        mma_chunk(&As[buf * 4608], &Ws[buf * 4224], acc, wm, wn, rowg, colg);
        __syncthreads();
    }

    const int cbase = c0 + wn * 32 + colg * 8;
#pragma unroll
    for (int r = 0; r < 8; r++) {
        int row = r0 + wm * 64 + r * 8 + rowg;
        float2 u0 = unpk2(acc[r][0]), u1 = unpk2(acc[r][1]);
        float2 u2 = unpk2(acc[r][2]), u3 = unpk2(acc[r][3]);
        float4 v0 = {u0.x, u0.y, u1.x, u1.y};
        float4 v1 = {u2.x, u2.y, u3.x, u3.y};
        *(float4*)&dst[(size_t)row * kD + cbase] = v0;
        *(float4*)&dst[(size_t)row * kD + cbase + 4] = v1;
    }
}

// ---------------------------------------------------------------------------
// Kernel 3b: out = sum of 8 partials + b0
// ---------------------------------------------------------------------------
__global__ __launch_bounds__(256)
void out_combine(const float* __restrict__ b0, float* __restrict__ out)
{
    int i4 = blockIdx.x * 256 + threadIdx.x;     // float4 index, 262144 total
    size_t off = (size_t)i4 * 4;
    float4 s = *(const float4*)&g_part8[0][off];
#pragma unroll
    for (int z = 1; z < 8; z++) {
        float4 p = *(const float4*)&g_part8[z][off];
        s.x += p.x; s.y += p.y; s.z += p.z; s.w += p.w;
    }
    float4 bb = *(const float4*)&b0[(i4 & 63) * 4];
    s.x += bb.x; s.y += bb.y; s.z += bb.z; s.w += bb.w;
    *(float4*)&out[off] = s;
}

// ---------------------------------------------------------------------------
extern "C" void kernel_launch(void* const* d_in, const int* in_sizes, int n_in,
                              void* d_out, int out_size)
{
    const float *x = nullptr, *Wqkv = nullptr, *bqkv = nullptr,
                *W0 = nullptr, *b0 = nullptr;
    for (int i = 0; i < n_in; i++) {
        switch (in_sizes[i]) {
            case kRows * kD: x    = (const float*)d_in[i]; break;
            case kD * kC3:   Wqkv = (const float*)d_in[i]; break;
            case kC3:        bqkv = (const float*)d_in[i]; break;
            case kDH * kD:   W0   = (const float*)d_in[i]; break;
            case kD:         b0   = (const float*)d_in[i]; break;
            default: break;
        }
    }
    float* out = (float*)d_out;

    const size_t smem1 = (size_t)(2 * 4608 + 2 * 4224) * sizeof(float);              // 70656
    const size_t smem2 = (size_t)(2 * 4608 + 2 * 4224 + 2048 + 128) * sizeof(float); // 79360
    const size_t smem3 = (size_t)(2 * 4608 + 2 * 4224 + 1024) * sizeof(float);       // 74752
    static bool attr_done = false;
    if (!attr_done) {
        cudaFuncSetAttribute(qkv_gemm_kernel,
                             cudaFuncAttributeMaxDynamicSharedMemorySize, (int)smem1);
        cudaFuncSetAttribute(score_diag_kernel,
                             cudaFuncAttributeMaxDynamicSharedMemorySize, (int)smem2);
        cudaFuncSetAttribute(out_gemm_kernel,
                             cudaFuncAttributeMaxDynamicSharedMemorySize, (int)smem3);
        attr_done = true;
    }

    qkv_gemm_kernel<<<dim3(kC3 / 128, kRows / 128), 256, smem1>>>(x, Wqkv, bqkv);
    transpose_qk_kernel<<<2048, 256>>>();
    score_diag_kernel<<<dim3(kN / 128, kB * kH, 4), 256, smem2>>>();
    finish_diag<<<128, 256>>>();
    out_gemm_kernel<<<dim3(kD / 128, kRows / 128, 8), 256, smem3>>>(W0);
    out_combine<<<1024, 256>>>(b0, out);
}

// round 13
// speedup vs baseline: 1.1190x; 1.0054x over previous
#include <cuda_runtime.h>
#include <cstdint>

// Problem constants
constexpr int kB = 4;
constexpr int kN = 1024;
constexpr int kD = 256;
constexpr int kH = 8;
constexpr int kDH  = kD * kH;          // 2048
constexpr int kNDH = kN * kDH;         // 2097152
constexpr int kSeg = kB * kNDH;        // 8388608  (q/k/v segment, floats)
constexpr int kC3  = 3 * kDH;          // 6144
constexpr int kRows = kB * kN;         // 4096

// Scratch (device globals; no dynamic allocation allowed)
__device__ float g_qkv[3ull * kSeg];   // ~100.7 MB : QKV in reference flat layout
__device__ float g_qkT[2ull * kSeg];   // seg0: Q n-major scaled [bh][n][d]; reused as Av
                                       // seg1: K d-major       [bh][d][n]
__device__ float g_diag[kRows * kH];
__device__ float g_pcs[4 * 32 * kN];      // k2 partial colsums [z][bh][n]
__device__ float g_diagexp[32 * kN];      // exp(S[n,n]) per [bh][n]
__device__ float g_part8[8][kRows * kD];  // k3 K-split partials (32 MB)

// ---------------- cp.async helpers ----------------
__device__ __forceinline__ void cp16(void* smem_dst, const void* gmem_src) {
    unsigned s = (unsigned)__cvta_generic_to_shared(smem_dst);
    asm volatile("cp.async.cg.shared.global [%0], [%1], 16;\n" :: "r"(s), "l"(gmem_src));
}
__device__ __forceinline__ void cp_commit() {
    asm volatile("cp.async.commit_group;\n");
}
template <int N>
__device__ __forceinline__ void cp_wait() {
    asm volatile("cp.async.wait_group %0;\n" :: "n"(N));
}

// ---------------- packed f32x2 helpers (Blackwell FFMA2) ----------------
__device__ __forceinline__ void ffma2(uint64_t& d, uint64_t a, uint64_t b) {
    asm("fma.rn.f32x2 %0, %1, %2, %0;" : "+l"(d) : "l"(a), "l"(b));
}
__device__ __forceinline__ uint64_t bcast2(float x) {
    uint64_t r;
    asm("mov.b64 %0, {%1, %1};" : "=l"(r) : "r"(__float_as_uint(x)));
    return r;
}
__device__ __forceinline__ float2 unpk2(uint64_t v) {
    uint32_t lo, hi;
    asm("mov.b64 {%0, %1}, %2;" : "=r"(lo), "=r"(hi) : "l"(v));
    return make_float2(__uint_as_float(lo), __uint_as_float(hi));
}
__device__ __forceinline__ float selc(float4 v, int kk) {
    return (kk == 0) ? v.x : (kk == 1) ? v.y : (kk == 2) ? v.z : v.w;
}

// Shared inner-loop: one 32-k chunk of a 128x128 tile.
// A_ m-major [128][36]; B_ k-major [32][132].
// Thread owns rows (wm*64 + r*8 + rowg), cols (wn*32 + colg*8 + 0..7).
__device__ __forceinline__ void mma_chunk(const float* __restrict__ A_,
                                          const float* __restrict__ B_,
                                          uint64_t (&acc)[8][4],
                                          int wm, int wn, int rowg, int colg)
{
#pragma unroll
    for (int kg = 0; kg < 32; kg += 4) {
        float4 av[8];
#pragma unroll
        for (int r = 0; r < 8; r++)
            av[r] = *(const float4*)&A_[(wm * 64 + r * 8 + rowg) * 36 + kg];
#pragma unroll
        for (int kk = 0; kk < 4; kk++) {
            const float* brow = &B_[(kg + kk) * 132 + wn * 32 + colg * 8];
            ulonglong2 q0 = *(const ulonglong2*)brow;
            ulonglong2 q1 = *(const ulonglong2*)(brow + 4);
#pragma unroll
            for (int r = 0; r < 8; r++) {
                uint64_t a2 = bcast2(selc(av[r], kk));
                ffma2(acc[r][0], a2, q0.x);
                ffma2(acc[r][1], a2, q0.y);
                ffma2(acc[r][2], a2, q1.x);
                ffma2(acc[r][3], a2, q1.y);
            }
        }
    }
}

// ---------------------------------------------------------------------------
// Kernel 1: QKV = x @ Wqkv + bqkv     [4096,256] @ [256,6144]
// CTA 128x128, warp 64x32, thread 8x8 packed, single-sync pipeline.
// grid(48, 32) = 1536 CTAs.
// ---------------------------------------------------------------------------
__global__ __launch_bounds__(256, 2)
void qkv_gemm_kernel(const float* __restrict__ x,
                     const float* __restrict__ W,
                     const float* __restrict__ bias)
{
    extern __shared__ float sm[];
    float* As = sm;                 // [2][128*36]
    float* Bs = sm + 2 * 4608;      // [2][32*132]

    const int t = threadIdx.x, lane = t & 31, w = t >> 5;
    const int wm = w & 1, wn = w >> 1;
    const int rowg = lane >> 2, colg = lane & 3;
    const int r0 = blockIdx.y * 128, c0 = blockIdx.x * 128;

    const int ar = t >> 3, ap = t & 7;
    const int bp = t & 31, br = t >> 5;

    uint64_t acc[8][4] = {};

    auto issue = [&](int buf, int kc) {
#pragma unroll
        for (int j = 0; j < 4; j++) {
            int m = ar + 32 * j;
            cp16(&As[buf * 4608 + m * 36 + ap * 4],
                 &x[(size_t)(r0 + m) * kD + kc + ap * 4]);
        }
#pragma unroll
        for (int i = 0; i < 4; i++) {
            int k = br + 8 * i;
            cp16(&Bs[buf * 4224 + k * 132 + bp * 4],
                 &W[(size_t)(kc + k) * kC3 + c0 + bp * 4]);
        }
        cp_commit();
    };

    issue(0, 0);
    for (int c = 0; c < 8; c++) {
        const int buf = c & 1;
        cp_wait<0>();
        __syncthreads();   // chunk c in; everyone done with mma(c-1) on buf^1
        if (c < 7) issue(buf ^ 1, (c + 1) * 32);
        mma_chunk(&As[buf * 4608], &Bs[buf * 4224], acc, wm, wn, rowg, colg);
    }

    const int cbase = c0 + wn * 32 + colg * 8;
#pragma unroll
    for (int r = 0; r < 8; r++) {
        int row = r0 + wm * 64 + r * 8 + rowg;
        float2 u0 = unpk2(acc[r][0]), u1 = unpk2(acc[r][1]);
        float2 u2 = unpk2(acc[r][2]), u3 = unpk2(acc[r][3]);
        float4 v0, v1;
        v0.x = u0.x + bias[cbase + 0]; v0.y = u0.y + bias[cbase + 1];
        v0.z = u1.x + bias[cbase + 2]; v0.w = u1.y + bias[cbase + 3];
        v1.x = u2.x + bias[cbase + 4]; v1.y = u2.y + bias[cbase + 5];
        v1.z = u3.x + bias[cbase + 6]; v1.w = u3.y + bias[cbase + 7];
        *(float4*)&g_qkv[(size_t)row * kC3 + cbase] = v0;
        *(float4*)&g_qkv[(size_t)row * kC3 + cbase + 4] = v1;
    }
}

// ---------------------------------------------------------------------------
// Transpose: q -> [bh][n][d] (scaled 1/16);  k -> [bh][d][n] (d-major).
// (proven version, verbatim)
// ---------------------------------------------------------------------------
__global__ __launch_bounds__(256)
void transpose_qk_kernel()
{
    __shared__ float smt[8][32][33];   // [h][qd][n]
    const int bid = blockIdx.x;
    const int qb  = bid & 7;
    const int nb  = (bid >> 3) & 31;
    const int b   = (bid >> 8) & 3;
    const int seg = bid >> 10;
    const int t   = threadIdx.x;

    const float* src = g_qkv + (size_t)seg * kSeg + (size_t)b * kNDH
                     + (size_t)(nb * 32) * kDH + qb * 32 * 8;
    {
        const int nl = t >> 3, f = t & 7;
        const int h0 = (f & 1) * 4, q0 = f >> 1;
#pragma unroll
        for (int i = 0; i < 8; i++) {
            float4 v = *(const float4*)&src[(size_t)nl * kDH + (f + i * 8) * 4];
            int ql = q0 + i * 4;
            smt[h0 + 0][ql][nl] = v.x;
            smt[h0 + 1][ql][nl] = v.y;
            smt[h0 + 2][ql][nl] = v.z;
            smt[h0 + 3][ql][nl] = v.w;
        }
    }
    __syncthreads();
    if (seg == 0) {
        const int q4 = (t & 7) * 4, hn = t >> 3;
#pragma unroll
        for (int i = 0; i < 8; i++) {
            int idx = hn + i * 32;
            int h = idx >> 5, n = idx & 31;
            float4 v;
            v.x = smt[h][q4 + 0][n] * 0.0625f;
            v.y = smt[h][q4 + 1][n] * 0.0625f;
            v.z = smt[h][q4 + 2][n] * 0.0625f;
            v.w = smt[h][q4 + 3][n] * 0.0625f;
            float* dst = g_qkT
                       + (((size_t)(b * 8 + h) * kN + nb * 32 + n) * kD)
                       + qb * 32 + q4;
            *(float4*)dst = v;
        }
    } else {
#pragma unroll
        for (int i = 0; i < 8; i++) {
            int idx = t + i * 256;
            int h = idx >> 8, rem = idx & 255;
            int q = rem >> 3, nf = rem & 7;
            float4 v;
            v.x = smt[h][q][nf * 4 + 0];
            v.y = smt[h][q][nf * 4 + 1];
            v.z = smt[h][q][nf * 4 + 2];
            v.w = smt[h][q][nf * 4 + 3];
            float* dst = g_qkT + (size_t)kSeg
                       + (((size_t)(b * 8 + h) * kD + qb * 32 + q) * kN)
                       + nb * 32 + nf * 4;
            *(float4*)dst = v;
        }
    }
}

// ---------------------------------------------------------------------------
// Kernel 2: per (b,h,msplit): partial colsums of exp(S) over 2 m-tiles of 128,
// plus diag-exp when owned. Single-sync pipeline. grid(8, 32, 4) = 1024 CTAs.
// ---------------------------------------------------------------------------
__global__ __launch_bounds__(256, 2)
void score_diag_kernel()
{
    extern __shared__ float sm[];
    float* As     = sm;                        // [2][128*36]
    float* Ks     = sm + 2 * 4608;             // [2][32*132]
    float* red    = sm + 2 * 4608 + 2 * 4224;  // [16*128]
    float* diagsm = red + 2048;                // [128]

    const int t = threadIdx.x, lane = t & 31, w = t >> 5;
    const int wm = w & 1, wn = w >> 1;
    const int rowg = lane >> 2, colg = lane & 3;
    const int bh = blockIdx.y;
    const int n0 = blockIdx.x * 128;
    const int z  = blockIdx.z;                 // m-split 0..3

    const float* Q  = g_qkT + (size_t)bh * (kN * kD);                 // [n][d]
    const float* Kd = g_qkT + (size_t)kSeg + (size_t)bh * (kD * kN);  // [d][n]

    const int ar = t >> 3, ap = t & 7;
    const int bp = t & 31, br = t >> 5;

    float colsum[8];
#pragma unroll
    for (int j = 0; j < 8; j++) colsum[j] = 0.f;

    const bool owner = ((int)blockIdx.x >> 1) == z;

    for (int mt = 2 * z; mt < 2 * z + 2; mt++) {
        const int m0 = mt * 128;
        uint64_t acc[8][4] = {};

        auto issue = [&](int buf, int kc) {
#pragma unroll
            for (int j = 0; j < 4; j++) {
                int m = ar + 32 * j;
                cp16(&As[buf * 4608 + m * 36 + ap * 4],
                     &Q[(size_t)(m0 + m) * kD + kc + ap * 4]);
            }
#pragma unroll
            for (int i = 0; i < 4; i++) {
                int k = br + 8 * i;
                cp16(&Ks[buf * 4224 + k * 132 + bp * 4],
                     &Kd[(size_t)(kc + k) * kN + n0 + bp * 4]);
            }
            cp_commit();
        };

        issue(0, 0);
        for (int c = 0; c < 8; c++) {
            const int buf = c & 1;
            cp_wait<0>();
            __syncthreads();
            if (c < 7) issue(buf ^ 1, (c + 1) * 32);
            mma_chunk(&As[buf * 4608], &Ks[buf * 4224], acc, wm, wn, rowg, colg);
        }

        // ---- epilogue: exp + colsum (registers); diagonal -> smem ----
        const bool diagtile = (mt == (int)blockIdx.x);
        const int clb = wn * 32 + colg * 8;
#pragma unroll
        for (int jp = 0; jp < 4; jp++) {
            float s0 = 0.f, s1 = 0.f;
#pragma unroll
            for (int r = 0; r < 8; r++) {
                float2 u = unpk2(acc[r][jp]);
                float e0 = __expf(u.x), e1 = __expf(u.y);
                s0 += e0; s1 += e1;
                if (diagtile) {
                    int lm = wm * 64 + r * 8 + rowg;
                    if (lm == clb + 2 * jp)     diagsm[clb + 2 * jp]     = e0;
                    if (lm == clb + 2 * jp + 1) diagsm[clb + 2 * jp + 1] = e1;
                }
            }
            colsum[2 * jp]     += s0;
            colsum[2 * jp + 1] += s1;
        }
    }

    // ---- reduction across the 16 (wm,rowg) slots; write partials ----
    const int slot = wm * 8 + rowg;
    const int clb = wn * 32 + colg * 8;
#pragma unroll
    for (int j = 0; j < 8; j++)
        red[slot * 128 + clb + j] = colsum[j];
    __syncthreads();
    if (t < 128) {
        float total = red[t];
#pragma unroll
        for (int r = 1; r < 16; r++) total += red[r * 128 + t];
        g_pcs[((size_t)z * 32 + bh) * kN + n0 + t] = total;
        if (owner)
            g_diagexp[(size_t)bh * kN + n0 + t] = diagsm[t];
    }
}

// ---------------------------------------------------------------------------
// Kernel 2b: g_diag = diagexp / sum_z pcs
// ---------------------------------------------------------------------------
__global__ __launch_bounds__(256)
void finish_diag()
{
    int id = blockIdx.x * 256 + threadIdx.x;   // 32768 = 32 bh x 1024 n
    int bh = id >> 10, n = id & 1023;
    float tot = g_pcs[(size_t)bh * kN + n]
              + g_pcs[((size_t)32 + bh) * kN + n]
              + g_pcs[((size_t)64 + bh) * kN + n]
              + g_pcs[((size_t)96 + bh) * kN + n];
    int b = bh >> 3, h = bh & 7;
    g_diag[((size_t)b * kN + n) * kH + h] = g_diagexp[(size_t)bh * kN + n] / tot;
}

// ---------------------------------------------------------------------------
// Kernel 2c: Av = diag .* v  -> g_qkT seg0 (Q is dead after k2)
// ---------------------------------------------------------------------------
__global__ __launch_bounds__(256)
void av_kernel()
{
    const float* vseg = g_qkv + 2ull * kSeg;
    int idx = (blockIdx.x * 256 + threadIdx.x) * 4;   // 8388608 elems total
    int r = idx >> 11;
    int c = idx & 2047;
    float4 v = *(const float4*)&vseg[idx];
    float4 dv = *(const float4*)&g_diag[r * 8 + (c & 4)];
    v.x *= dv.x; v.y *= dv.y; v.z *= dv.z; v.w *= dv.w;
    *(float4*)&g_qkT[idx] = v;
}

// ---------------------------------------------------------------------------
// Kernel 3: partial = Av @ W0, K-split 8.  [4096,2048]@[2048,256]
// Pure cp.async both operands, single-sync pipeline.
// grid(2 ctiles, 32 mtiles, 8 ksplit) = 1024 CTAs.
// ---------------------------------------------------------------------------
__global__ __launch_bounds__(256, 2)
void out_gemm_kernel(const float* __restrict__ W0)
{
    extern __shared__ float sm[];
    float* As = sm;                 // [2][128*36]
    float* Ws = sm + 2 * 4608;      // [2][32*132]

    const int t = threadIdx.x, lane = t & 31, w = t >> 5;
    const int wm = w & 1, wn = w >> 1;
    const int rowg = lane >> 2, colg = lane & 3;
    const int c0 = blockIdx.x * 128;
    const int r0 = blockIdx.y * 128;
    const int kb = blockIdx.z * 256;
    float* dst = g_part8[blockIdx.z];

    const int ar = t >> 3, ap = t & 7;
    const int bp = t & 31, br = t >> 5;

    uint64_t acc[8][4] = {};

    auto issue = [&](int buf, int kc) {
#pragma unroll
        for (int j = 0; j < 4; j++) {
            int m = ar + 32 * j;
            cp16(&As[buf * 4608 + m * 36 + ap * 4],
                 &g_qkT[(size_t)(r0 + m) * kDH + kb + kc + ap * 4]);
        }
#pragma unroll
        for (int i = 0; i < 4; i++) {
            int k = br + 8 * i;
            cp16(&Ws[buf * 4224 + k * 132 + bp * 4],
                 &W0[(size_t)(kb + kc + k) * kD + c0 + bp * 4]);
        }
        cp_commit();
    };

    issue(0, 0);
    for (int c = 0; c < 8; c++) {
        const int buf = c & 1;
        cp_wait<0>();
        __syncthreads();
        if (c < 7) issue(buf ^ 1, (c + 1) * 32);
        mma_chunk(&As[buf * 4608], &Ws[buf * 4224], acc, wm, wn, rowg, colg);
    }

    const int cbase = c0 + wn * 32 + colg * 8;
#pragma unroll
    for (int r = 0; r < 8; r++) {
        int row = r0 + wm * 64 + r * 8 + rowg;
        float2 u0 = unpk2(acc[r][0]), u1 = unpk2(acc[r][1]);
        float2 u2 = unpk2(acc[r][2]), u3 = unpk2(acc[r][3]);
        float4 v0 = {u0.x, u0.y, u1.x, u1.y};
        float4 v1 = {u2.x, u2.y, u3.x, u3.y};
        *(float4*)&dst[(size_t)row * kD + cbase] = v0;
        *(float4*)&dst[(size_t)row * kD + cbase + 4] = v1;
    }
}

// ---------------------------------------------------------------------------
// Kernel 3b: out = sum of 8 partials + b0
// ---------------------------------------------------------------------------
__global__ __launch_bounds__(256)
void out_combine(const float* __restrict__ b0, float* __restrict__ out)
{
    int i4 = blockIdx.x * 256 + threadIdx.x;     // float4 index, 262144 total
    size_t off = (size_t)i4 * 4;
    float4 s = *(const float4*)&g_part8[0][off];
#pragma unroll
    for (int z = 1; z < 8; z++) {
        float4 p = *(const float4*)&g_part8[z][off];
        s.x += p.x; s.y += p.y; s.z += p.z; s.w += p.w;
    }
    float4 bb = *(const float4*)&b0[(i4 & 63) * 4];
    s.x += bb.x; s.y += bb.y; s.z += bb.z; s.w += bb.w;
    *(float4*)&out[off] = s;
}

// ---------------------------------------------------------------------------
extern "C" void kernel_launch(void* const* d_in, const int* in_sizes, int n_in,
                              void* d_out, int out_size)
{
    const float *x = nullptr, *Wqkv = nullptr, *bqkv = nullptr,
                *W0 = nullptr, *b0 = nullptr;
    for (int i = 0; i < n_in; i++) {
        switch (in_sizes[i]) {
            case kRows * kD: x    = (const float*)d_in[i]; break;
            case kD * kC3:   Wqkv = (const float*)d_in[i]; break;
            case kC3:        bqkv = (const float*)d_in[i]; break;
            case kDH * kD:   W0   = (const float*)d_in[i]; break;
            case kD:         b0   = (const float*)d_in[i]; break;
            default: break;
        }
    }
    float* out = (float*)d_out;

    const size_t smem1 = (size_t)(2 * 4608 + 2 * 4224) * sizeof(float);              // 70656
    const size_t smem2 = (size_t)(2 * 4608 + 2 * 4224 + 2048 + 128) * sizeof(float); // 79360
    const size_t smem3 = (size_t)(2 * 4608 + 2 * 4224) * sizeof(float);              // 70656
    static bool attr_done = false;
    if (!attr_done) {
        cudaFuncSetAttribute(qkv_gemm_kernel,
                             cudaFuncAttributeMaxDynamicSharedMemorySize, (int)smem1);
        cudaFuncSetAttribute(score_diag_kernel,
                             cudaFuncAttributeMaxDynamicSharedMemorySize, (int)smem2);
        cudaFuncSetAttribute(out_gemm_kernel,
                             cudaFuncAttributeMaxDynamicSharedMemorySize, (int)smem3);
        attr_done = true;
    }

    qkv_gemm_kernel<<<dim3(kC3 / 128, kRows / 128), 256, smem1>>>(x, Wqkv, bqkv);
    transpose_qk_kernel<<<2048, 256>>>();
    score_diag_kernel<<<dim3(kN / 128, kB * kH, 4), 256, smem2>>>();
    finish_diag<<<128, 256>>>();
    av_kernel<<<8192, 256>>>();
    out_gemm_kernel<<<dim3(kD / 128, kRows / 128, 8), 256, smem3>>>(W0);
    out_combine<<<1024, 256>>>(b0, out);
}

// round 14
// speedup vs baseline: 1.1287x; 1.0087x over previous
#include <cuda_runtime.h>
#include <cstdint>

// Problem constants
constexpr int kB = 4;
constexpr int kN = 1024;
constexpr int kD = 256;
constexpr int kH = 8;
constexpr int kDH  = kD * kH;          // 2048
constexpr int kNDH = kN * kDH;         // 2097152
constexpr int kSeg = kB * kNDH;        // 8388608  (q/k/v segment, floats)
constexpr int kC3  = 3 * kDH;          // 6144
constexpr int kRows = kB * kN;         // 4096

// Scratch (device globals; no dynamic allocation allowed)
__device__ float g_qkv[3ull * kSeg];   // ~100.7 MB : QKV in reference flat layout
__device__ float g_qkT[2ull * kSeg];   // seg0: Q n-major scaled [bh][n][d]; reused as Av
                                       // seg1: K d-major       [bh][d][n]
__device__ float g_diag[kRows * kH];
__device__ float g_pcs[8 * 32 * kN];      // k2 partial colsums [z][bh][n]
__device__ float g_diagexp[32 * kN];      // exp(S[n,n]) per [bh][n]
__device__ float g_part8[8][kRows * kD];  // k3 K-split partials (32 MB)

// ---------------- cp.async helpers ----------------
__device__ __forceinline__ void cp16(void* smem_dst, const void* gmem_src) {
    unsigned s = (unsigned)__cvta_generic_to_shared(smem_dst);
    asm volatile("cp.async.cg.shared.global [%0], [%1], 16;\n" :: "r"(s), "l"(gmem_src));
}
__device__ __forceinline__ void cp_commit() {
    asm volatile("cp.async.commit_group;\n");
}
template <int N>
__device__ __forceinline__ void cp_wait() {
    asm volatile("cp.async.wait_group %0;\n" :: "n"(N));
}

// ---------------- packed f32x2 helpers (Blackwell FFMA2) ----------------
__device__ __forceinline__ void ffma2(uint64_t& d, uint64_t a, uint64_t b) {
    asm("fma.rn.f32x2 %0, %1, %2, %0;" : "+l"(d) : "l"(a), "l"(b));
}
__device__ __forceinline__ uint64_t bcast2(float x) {
    uint64_t r;
    asm("mov.b64 %0, {%1, %1};" : "=l"(r) : "r"(__float_as_uint(x)));
    return r;
}
__device__ __forceinline__ float2 unpk2(uint64_t v) {
    uint32_t lo, hi;
    asm("mov.b64 {%0, %1}, %2;" : "=r"(lo), "=r"(hi) : "l"(v));
    return make_float2(__uint_as_float(lo), __uint_as_float(hi));
}
__device__ __forceinline__ float selc(float4 v, int kk) {
    return (kk == 0) ? v.x : (kk == 1) ? v.y : (kk == 2) ? v.z : v.w;
}

// Shared inner-loop: one 32-k chunk of a 128x128 tile.
// A_ m-major [128][36]; B_ k-major [32][132].
__device__ __forceinline__ void mma_chunk(const float* __restrict__ A_,
                                          const float* __restrict__ B_,
                                          uint64_t (&acc)[8][4],
                                          int wm, int wn, int rowg, int colg)
{
#pragma unroll
    for (int kg = 0; kg < 32; kg += 4) {
        float4 av[8];
#pragma unroll
        for (int r = 0; r < 8; r++)
            av[r] = *(const float4*)&A_[(wm * 64 + r * 8 + rowg) * 36 + kg];
#pragma unroll
        for (int kk = 0; kk < 4; kk++) {
            const float* brow = &B_[(kg + kk) * 132 + wn * 32 + colg * 8];
            ulonglong2 q0 = *(const ulonglong2*)brow;
            ulonglong2 q1 = *(const ulonglong2*)(brow + 4);
#pragma unroll
            for (int r = 0; r < 8; r++) {
                uint64_t a2 = bcast2(selc(av[r], kk));
                ffma2(acc[r][0], a2, q0.x);
                ffma2(acc[r][1], a2, q0.y);
                ffma2(acc[r][2], a2, q1.x);
                ffma2(acc[r][3], a2, q1.y);
            }
        }
    }
}

// 64-row variant for k3 (CTA 64m x 128n, thread 4x8).
__device__ __forceinline__ void mma_chunk64(const float* __restrict__ A_,
                                            const float* __restrict__ B_,
                                            uint64_t (&acc)[4][4],
                                            int wm, int wn, int rowg, int colg)
{
#pragma unroll
    for (int kg = 0; kg < 32; kg += 4) {
        float4 av[4];
#pragma unroll
        for (int r = 0; r < 4; r++)
            av[r] = *(const float4*)&A_[(wm * 32 + r * 8 + rowg) * 36 + kg];
#pragma unroll
        for (int kk = 0; kk < 4; kk++) {
            const float* brow = &B_[(kg + kk) * 132 + wn * 32 + colg * 8];
            ulonglong2 q0 = *(const ulonglong2*)brow;
            ulonglong2 q1 = *(const ulonglong2*)(brow + 4);
#pragma unroll
            for (int r = 0; r < 4; r++) {
                uint64_t a2 = bcast2(selc(av[r], kk));
                ffma2(acc[r][0], a2, q0.x);
                ffma2(acc[r][1], a2, q0.y);
                ffma2(acc[r][2], a2, q1.x);
                ffma2(acc[r][3], a2, q1.y);
            }
        }
    }
}

// ---------------------------------------------------------------------------
// Kernel 1: QKV = x @ Wqkv + bqkv     [4096,256] @ [256,6144]
// CTA 128x128, warp 64x32, thread 8x8 packed, single-sync pipeline.
// grid(48, 32) = 1536 CTAs. (proven, verbatim)
// ---------------------------------------------------------------------------
__global__ __launch_bounds__(256, 2)
void qkv_gemm_kernel(const float* __restrict__ x,
                     const float* __restrict__ W,
                     const float* __restrict__ bias)
{
    extern __shared__ float sm[];
    float* As = sm;                 // [2][128*36]
    float* Bs = sm + 2 * 4608;      // [2][32*132]

    const int t = threadIdx.x, lane = t & 31, w = t >> 5;
    const int wm = w & 1, wn = w >> 1;
    const int rowg = lane >> 2, colg = lane & 3;
    const int r0 = blockIdx.y * 128, c0 = blockIdx.x * 128;

    const int ar = t >> 3, ap = t & 7;
    const int bp = t & 31, br = t >> 5;

    uint64_t acc[8][4] = {};

    auto issue = [&](int buf, int kc) {
#pragma unroll
        for (int j = 0; j < 4; j++) {
            int m = ar + 32 * j;
            cp16(&As[buf * 4608 + m * 36 + ap * 4],
                 &x[(size_t)(r0 + m) * kD + kc + ap * 4]);
        }
#pragma unroll
        for (int i = 0; i < 4; i++) {
            int k = br + 8 * i;
            cp16(&Bs[buf * 4224 + k * 132 + bp * 4],
                 &W[(size_t)(kc + k) * kC3 + c0 + bp * 4]);
        }
        cp_commit();
    };

    issue(0, 0);
    for (int c = 0; c < 8; c++) {
        const int buf = c & 1;
        cp_wait<0>();
        __syncthreads();
        if (c < 7) issue(buf ^ 1, (c + 1) * 32);
        mma_chunk(&As[buf * 4608], &Bs[buf * 4224], acc, wm, wn, rowg, colg);
    }

    const int cbase = c0 + wn * 32 + colg * 8;
#pragma unroll
    for (int r = 0; r < 8; r++) {
        int row = r0 + wm * 64 + r * 8 + rowg;
        float2 u0 = unpk2(acc[r][0]), u1 = unpk2(acc[r][1]);
        float2 u2 = unpk2(acc[r][2]), u3 = unpk2(acc[r][3]);
        float4 v0, v1;
        v0.x = u0.x + bias[cbase + 0]; v0.y = u0.y + bias[cbase + 1];
        v0.z = u1.x + bias[cbase + 2]; v0.w = u1.y + bias[cbase + 3];
        v1.x = u2.x + bias[cbase + 4]; v1.y = u2.y + bias[cbase + 5];
        v1.z = u3.x + bias[cbase + 6]; v1.w = u3.y + bias[cbase + 7];
        *(float4*)&g_qkv[(size_t)row * kC3 + cbase] = v0;
        *(float4*)&g_qkv[(size_t)row * kC3 + cbase + 4] = v1;
    }
}

// ---------------------------------------------------------------------------
// Transpose: q -> [bh][n][d] (scaled 1/16);  k -> [bh][d][n] (d-major).
// (proven, verbatim)
// ---------------------------------------------------------------------------
__global__ __launch_bounds__(256)
void transpose_qk_kernel()
{
    __shared__ float smt[8][32][33];   // [h][qd][n]
    const int bid = blockIdx.x;
    const int qb  = bid & 7;
    const int nb  = (bid >> 3) & 31;
    const int b   = (bid >> 8) & 3;
    const int seg = bid >> 10;
    const int t   = threadIdx.x;

    const float* src = g_qkv + (size_t)seg * kSeg + (size_t)b * kNDH
                     + (size_t)(nb * 32) * kDH + qb * 32 * 8;
    {
        const int nl = t >> 3, f = t & 7;
        const int h0 = (f & 1) * 4, q0 = f >> 1;
#pragma unroll
        for (int i = 0; i < 8; i++) {
            float4 v = *(const float4*)&src[(size_t)nl * kDH + (f + i * 8) * 4];
            int ql = q0 + i * 4;
            smt[h0 + 0][ql][nl] = v.x;
            smt[h0 + 1][ql][nl] = v.y;
            smt[h0 + 2][ql][nl] = v.z;
            smt[h0 + 3][ql][nl] = v.w;
        }
    }
    __syncthreads();
    if (seg == 0) {
        const int q4 = (t & 7) * 4, hn = t >> 3;
#pragma unroll
        for (int i = 0; i < 8; i++) {
            int idx = hn + i * 32;
            int h = idx >> 5, n = idx & 31;
            float4 v;
            v.x = smt[h][q4 + 0][n] * 0.0625f;
            v.y = smt[h][q4 + 1][n] * 0.0625f;
            v.z = smt[h][q4 + 2][n] * 0.0625f;
            v.w = smt[h][q4 + 3][n] * 0.0625f;
            float* dst = g_qkT
                       + (((size_t)(b * 8 + h) * kN + nb * 32 + n) * kD)
                       + qb * 32 + q4;
            *(float4*)dst = v;
        }
    } else {
#pragma unroll
        for (int i = 0; i < 8; i++) {
            int idx = t + i * 256;
            int h = idx >> 8, rem = idx & 255;
            int q = rem >> 3, nf = rem & 7;
            float4 v;
            v.x = smt[h][q][nf * 4 + 0];
            v.y = smt[h][q][nf * 4 + 1];
            v.z = smt[h][q][nf * 4 + 2];
            v.w = smt[h][q][nf * 4 + 3];
            float* dst = g_qkT + (size_t)kSeg
                       + (((size_t)(b * 8 + h) * kD + qb * 32 + q) * kN)
                       + nb * 32 + nf * 4;
            *(float4*)dst = v;
        }
    }
}

// ---------------------------------------------------------------------------
// Kernel 2: per (b,h,z): colsums of exp(S) for ONE 128-m tile (m0 = z*128),
// plus diag-exp when z == n-tile. Single m-tile per CTA: no drains.
// grid(8, 32, 8) = 2048 CTAs.
// ---------------------------------------------------------------------------
__global__ __launch_bounds__(256, 2)
void score_diag_kernel()
{
    extern __shared__ float sm[];
    float* As     = sm;                        // [2][128*36]
    float* Ks     = sm + 2 * 4608;             // [2][32*132]
    float* red    = sm + 2 * 4608 + 2 * 4224;  // [16*128]
    float* diagsm = red + 2048;                // [128]

    const int t = threadIdx.x, lane = t & 31, w = t >> 5;
    const int wm = w & 1, wn = w >> 1;
    const int rowg = lane >> 2, colg = lane & 3;
    const int bh = blockIdx.y;
    const int n0 = blockIdx.x * 128;
    const int z  = blockIdx.z;                 // m-tile 0..7
    const int m0 = z * 128;

    const float* Q  = g_qkT + (size_t)bh * (kN * kD);                 // [n][d]
    const float* Kd = g_qkT + (size_t)kSeg + (size_t)bh * (kD * kN);  // [d][n]

    const int ar = t >> 3, ap = t & 7;
    const int bp = t & 31, br = t >> 5;

    const bool diagtile = (z == (int)blockIdx.x);

    uint64_t acc[8][4] = {};

    auto issue = [&](int buf, int kc) {
#pragma unroll
        for (int j = 0; j < 4; j++) {
            int m = ar + 32 * j;
            cp16(&As[buf * 4608 + m * 36 + ap * 4],
                 &Q[(size_t)(m0 + m) * kD + kc + ap * 4]);
        }
#pragma unroll
        for (int i = 0; i < 4; i++) {
            int k = br + 8 * i;
            cp16(&Ks[buf * 4224 + k * 132 + bp * 4],
                 &Kd[(size_t)(kc + k) * kN + n0 + bp * 4]);
        }
        cp_commit();
    };

    issue(0, 0);
    for (int c = 0; c < 8; c++) {
        const int buf = c & 1;
        cp_wait<0>();
        __syncthreads();
        if (c < 7) issue(buf ^ 1, (c + 1) * 32);
        mma_chunk(&As[buf * 4608], &Ks[buf * 4224], acc, wm, wn, rowg, colg);
    }

    // ---- epilogue: exp + colsum; diagonal -> smem ----
    float colsum[8];
    const int clb = wn * 32 + colg * 8;
#pragma unroll
    for (int jp = 0; jp < 4; jp++) {
        float s0 = 0.f, s1 = 0.f;
#pragma unroll
        for (int r = 0; r < 8; r++) {
            float2 u = unpk2(acc[r][jp]);
            float e0 = __expf(u.x), e1 = __expf(u.y);
            s0 += e0; s1 += e1;
            if (diagtile) {
                int lm = wm * 64 + r * 8 + rowg;
                if (lm == clb + 2 * jp)     diagsm[clb + 2 * jp]     = e0;
                if (lm == clb + 2 * jp + 1) diagsm[clb + 2 * jp + 1] = e1;
            }
        }
        colsum[2 * jp]     = s0;
        colsum[2 * jp + 1] = s1;
    }

    // ---- reduction across the 16 (wm,rowg) slots; write partials ----
    const int slot = wm * 8 + rowg;
#pragma unroll
    for (int j = 0; j < 8; j++)
        red[slot * 128 + clb + j] = colsum[j];
    __syncthreads();
    if (t < 128) {
        float total = red[t];
#pragma unroll
        for (int r = 1; r < 16; r++) total += red[r * 128 + t];
        g_pcs[((size_t)z * 32 + bh) * kN + n0 + t] = total;
        if (diagtile)
            g_diagexp[(size_t)bh * kN + n0 + t] = diagsm[t];
    }
}

// ---------------------------------------------------------------------------
// Kernel 2b: g_diag = diagexp / sum_z pcs
// ---------------------------------------------------------------------------
__global__ __launch_bounds__(256)
void finish_diag()
{
    int id = blockIdx.x * 256 + threadIdx.x;   // 32768 = 32 bh x 1024 n
    int bh = id >> 10, n = id & 1023;
    float tot = 0.f;
#pragma unroll
    for (int z = 0; z < 8; z++)
        tot += g_pcs[((size_t)z * 32 + bh) * kN + n];
    int b = bh >> 3, h = bh & 7;
    g_diag[((size_t)b * kN + n) * kH + h] = g_diagexp[(size_t)bh * kN + n] / tot;
}

// ---------------------------------------------------------------------------
// Kernel 2c: Av = diag .* v  -> g_qkT seg0 (Q is dead after k2)
// ---------------------------------------------------------------------------
__global__ __launch_bounds__(256)
void av_kernel()
{
    const float* vseg = g_qkv + 2ull * kSeg;
    int idx = (blockIdx.x * 256 + threadIdx.x) * 4;   // 8388608 elems total
    int r = idx >> 11;
    int c = idx & 2047;
    float4 v = *(const float4*)&vseg[idx];
    float4 dv = *(const float4*)&g_diag[r * 8 + (c & 4)];
    v.x *= dv.x; v.y *= dv.y; v.z *= dv.z; v.w *= dv.w;
    *(float4*)&g_qkT[idx] = v;
}

// ---------------------------------------------------------------------------
// Kernel 3: partial = Av @ W0, K-split 8.  [4096,2048]@[2048,256]
// CTA 64m x 128n, thread 4x8 packed. grid(2, 64, 8) = 1024 CTAs.
// ---------------------------------------------------------------------------
__global__ __launch_bounds__(256, 2)
void out_gemm_kernel(const float* __restrict__ W0)
{
    extern __shared__ float sm[];
    float* As = sm;                 // [2][64*36]  = 2*2304
    float* Ws = sm + 2 * 2304;      // [2][32*132] = 2*4224

    const int t = threadIdx.x, lane = t & 31, w = t >> 5;
    const int wm = w & 1, wn = w >> 1;
    const int rowg = lane >> 2, colg = lane & 3;
    const int c0 = blockIdx.x * 128;
    const int r0 = blockIdx.y * 64;
    const int kb = blockIdx.z * 256;
    float* dst = g_part8[blockIdx.z];

    const int ar = t >> 3, ap = t & 7;
    const int bp = t & 31, br = t >> 5;

    uint64_t acc[4][4] = {};

    auto issue = [&](int buf, int kc) {
#pragma unroll
        for (int j = 0; j < 2; j++) {
            int m = ar + 32 * j;
            cp16(&As[buf * 2304 + m * 36 + ap * 4],
                 &g_qkT[(size_t)(r0 + m) * kDH + kb + kc + ap * 4]);
        }
#pragma unroll
        for (int i = 0; i < 4; i++) {
            int k = br + 8 * i;
            cp16(&Ws[buf * 4224 + k * 132 + bp * 4],
                 &W0[(size_t)(kb + kc + k) * kD + c0 + bp * 4]);
        }
        cp_commit();
    };

    issue(0, 0);
    for (int c = 0; c < 8; c++) {
        const int buf = c & 1;
        cp_wait<0>();
        __syncthreads();
        if (c < 7) issue(buf ^ 1, (c + 1) * 32);
        mma_chunk64(&As[buf * 2304], &Ws[buf * 4224], acc, wm, wn, rowg, colg);
    }

    const int cbase = c0 + wn * 32 + colg * 8;
#pragma unroll
    for (int r = 0; r < 4; r++) {
        int row = r0 + wm * 32 + r * 8 + rowg;
        float2 u0 = unpk2(acc[r][0]), u1 = unpk2(acc[r][1]);
        float2 u2 = unpk2(acc[r][2]), u3 = unpk2(acc[r][3]);
        float4 v0 = {u0.x, u0.y, u1.x, u1.y};
        float4 v1 = {u2.x, u2.y, u3.x, u3.y};
        *(float4*)&dst[(size_t)row * kD + cbase] = v0;
        *(float4*)&dst[(size_t)row * kD + cbase + 4] = v1;
    }
}

// ---------------------------------------------------------------------------
// Kernel 3b: out = sum of 8 partials + b0
// ---------------------------------------------------------------------------
__global__ __launch_bounds__(256)
void out_combine(const float* __restrict__ b0, float* __restrict__ out)
{
    int i4 = blockIdx.x * 256 + threadIdx.x;     // float4 index, 262144 total
    size_t off = (size_t)i4 * 4;
    float4 s = *(const float4*)&g_part8[0][off];
#pragma unroll
    for (int z = 1; z < 8; z++) {
        float4 p = *(const float4*)&g_part8[z][off];
        s.x += p.x; s.y += p.y; s.z += p.z; s.w += p.w;
    }
    float4 bb = *(const float4*)&b0[(i4 & 63) * 4];
    s.x += bb.x; s.y += bb.y; s.z += bb.z; s.w += bb.w;
    *(float4*)&out[off] = s;
}

// ---------------------------------------------------------------------------
extern "C" void kernel_launch(void* const* d_in, const int* in_sizes, int n_in,
                              void* d_out, int out_size)
{
    const float *x = nullptr, *Wqkv = nullptr, *bqkv = nullptr,
                *W0 = nullptr, *b0 = nullptr;
    for (int i = 0; i < n_in; i++) {
        switch (in_sizes[i]) {
            case kRows * kD: x    = (const float*)d_in[i]; break;
            case kD * kC3:   Wqkv = (const float*)d_in[i]; break;
            case kC3:        bqkv = (const float*)d_in[i]; break;
            case kDH * kD:   W0   = (const float*)d_in[i]; break;
            case kD:         b0   = (const float*)d_in[i]; break;
            default: break;
        }
    }
    float* out = (float*)d_out;

    const size_t smem1 = (size_t)(2 * 4608 + 2 * 4224) * sizeof(float);              // 70656
    const size_t smem2 = (size_t)(2 * 4608 + 2 * 4224 + 2048 + 128) * sizeof(float); // 79360
    const size_t smem3 = (size_t)(2 * 2304 + 2 * 4224) * sizeof(float);              // 52224
    static bool attr_done = false;
    if (!attr_done) {
        cudaFuncSetAttribute(qkv_gemm_kernel,
                             cudaFuncAttributeMaxDynamicSharedMemorySize, (int)smem1);
        cudaFuncSetAttribute(score_diag_kernel,
                             cudaFuncAttributeMaxDynamicSharedMemorySize, (int)smem2);
        cudaFuncSetAttribute(out_gemm_kernel,
                             cudaFuncAttributeMaxDynamicSharedMemorySize, (int)smem3);
        attr_done = true;
    }

    qkv_gemm_kernel<<<dim3(kC3 / 128, kRows / 128), 256, smem1>>>(x, Wqkv, bqkv);
    transpose_qk_kernel<<<2048, 256>>>();
    score_diag_kernel<<<dim3(kN / 128, kB * kH, 8), 256, smem2>>>();
    finish_diag<<<128, 256>>>();
    av_kernel<<<8192, 256>>>();
    out_gemm_kernel<<<dim3(kD / 128, kRows / 64, 8), 256, smem3>>>(W0);
    out_combine<<<1024, 256>>>(b0, out);
}